// round 2
// baseline (speedup 1.0000x reference)
#include <cuda_runtime.h>

#define GRP 16
#define BSZ 8192
#define CH  256

// ---------------- scratch (device globals; no allocation allowed) ----------
__device__ float g_beta[GRP * CH];
__device__ float g_G[GRP * CH * CH];     // G = V^T V
__device__ float g_Y[GRP * CH * CH];     // Y = V R^{-1}
__device__ float g_Q[GRP * CH * CH];     // Q = I - Y V^T

// ---------------- beta_i = 2 / (w_i . w_i) --------------------------------
__global__ void beta_kernel(const float* __restrict__ W) {
    int g = blockIdx.x, i = threadIdx.x;
    const float* Vg = W + g * CH * CH;
    float s = 0.f;
    #pragma unroll 8
    for (int r = 0; r < CH; ++r) {
        float v = Vg[r * CH + i];
        s += v * v;
    }
    g_beta[g * CH + i] = 2.0f / s;
}

// ---------------- G = V^T V  (64x64 tiles, k = rows of V) ------------------
__global__ void g_kernel(const float* __restrict__ W) {
    int g = blockIdx.z;
    int a0 = blockIdx.y * 64, b0 = blockIdx.x * 64;
    const float* Vg = W + g * CH * CH;

    __shared__ float As[32][68];   // stride 68 floats = 272 B, 16B-aligned rows
    __shared__ float Bs[32][68];

    int t = threadIdx.x;
    int ty = t >> 4, tx = t & 15;     // 16x16 threads, 4x4 micro-tile
    float acc[4][4] = {};

    for (int k0 = 0; k0 < CH; k0 += 32) {
        __syncthreads();
        for (int e = t; e < 32 * 64; e += 256) {
            int kk = e >> 6, aa = e & 63;
            As[kk][aa] = Vg[(k0 + kk) * CH + a0 + aa];
            Bs[kk][aa] = Vg[(k0 + kk) * CH + b0 + aa];
        }
        __syncthreads();
        #pragma unroll
        for (int k = 0; k < 32; ++k) {
            float4 av = *(const float4*)&As[k][ty * 4];
            float4 bv = *(const float4*)&Bs[k][tx * 4];
            float a[4] = {av.x, av.y, av.z, av.w};
            float b[4] = {bv.x, bv.y, bv.z, bv.w};
            #pragma unroll
            for (int i = 0; i < 4; ++i)
                #pragma unroll
                for (int j = 0; j < 4; ++j)
                    acc[i][j] += a[i] * b[j];
        }
    }
    float* Gg = g_G + g * CH * CH;
    #pragma unroll
    for (int i = 0; i < 4; ++i)
        #pragma unroll
        for (int j = 0; j < 4; ++j)
            Gg[(a0 + ty * 4 + i) * CH + b0 + tx * 4 + j] = acc[i][j];
}

// ---------------- Y = V R^{-1} ; R = diag(1/beta) + triu(G, 1) -------------
// Rows of Y are independent -> one CTA handles a 32-row block of one group
// and runs all 8 column-block phases locally with __syncthreads().
__global__ void y_kernel(const float* __restrict__ W) {
    int g  = blockIdx.y;
    int r0 = blockIdx.x * 32;

    __shared__ float Ys[32][261];   // scalar access only; odd pad for columns
    __shared__ float Gs[32][36];    // float4-read: stride 36 (144 B, aligned)
    __shared__ float Gd[32][33];    // scalar access only
    __shared__ float pre[32][33];   // scalar access only
    __shared__ float betas[CH];

    int t = threadIdx.x;            // 256 threads
    betas[t] = g_beta[g * CH + t];
    __syncthreads();

    const float* Vg = W   + g * CH * CH;
    const float* Gg = g_G + g * CH * CH;
    float*       Yg = g_Y + g * CH * CH;

    int r = t >> 3, q = t & 7;      // 32 rows x 8 col-quads

    for (int kb = 0; kb < 8; ++kb) {
        int c0 = kb * 32;
        // acc = V[r0+r][c0+4q .. +3]
        float4 v4 = *(const float4*)&Vg[(r0 + r) * CH + c0 + 4 * q];
        float acc[4] = {v4.x, v4.y, v4.z, v4.w};

        // acc -= Ys[r][j] * G[j][c]  for j < c0   (chunks of 32 j)
        for (int jc = 0; jc < kb; ++jc) {
            int j0 = jc * 32;
            __syncthreads();
            for (int e = t; e < 32 * 32; e += 256) {
                int jj = e >> 5, c = e & 31;
                Gs[jj][c] = Gg[(j0 + jj) * CH + c0 + c];
            }
            __syncthreads();
            #pragma unroll
            for (int jj = 0; jj < 32; ++jj) {
                float yv = Ys[r][j0 + jj];
                float4 gg = *(const float4*)&Gs[jj][4 * q];
                acc[0] -= yv * gg.x;
                acc[1] -= yv * gg.y;
                acc[2] -= yv * gg.z;
                acc[3] -= yv * gg.w;
            }
        }
        // stage pre + load diagonal block, then in-block triangular solve
        pre[r][4 * q + 0] = acc[0];
        pre[r][4 * q + 1] = acc[1];
        pre[r][4 * q + 2] = acc[2];
        pre[r][4 * q + 3] = acc[3];
        for (int e = t; e < 32 * 32; e += 256) {
            int jj = e >> 5, c = e & 31;
            Gd[jj][c] = Gg[(c0 + jj) * CH + c0 + c];
        }
        __syncthreads();
        if (t < 32) {
            int rr = t;
            #pragma unroll 1
            for (int c = 0; c < 32; ++c) {
                float v = pre[rr][c];
                for (int d = 0; d < c; ++d)
                    v -= Ys[rr][c0 + d] * Gd[d][c];
                Ys[rr][c0 + c] = v * betas[c0 + c];
            }
        }
        __syncthreads();
    }
    for (int e = t; e < 32 * CH; e += 256) {
        int rr = e >> 8, cc = e & 255;
        Yg[(r0 + rr) * CH + cc] = Ys[rr][cc];
    }
}

// ---------------- Q = I - Y V^T  (NT gemm, k contiguous in both) -----------
__global__ void q_kernel(const float* __restrict__ W) {
    int g = blockIdx.z;
    int a0 = blockIdx.y * 64, b0 = blockIdx.x * 64;
    const float* Yg = g_Y + g * CH * CH;
    const float* Vg = W   + g * CH * CH;

    __shared__ float As[32][68];   // 16B-aligned rows
    __shared__ float Bs[32][68];

    int t = threadIdx.x;
    int ty = t >> 4, tx = t & 15;
    float acc[4][4] = {};

    for (int k0 = 0; k0 < CH; k0 += 32) {
        __syncthreads();
        for (int e = t; e < 64 * 32; e += 256) {
            int aa = e >> 5, kk = e & 31;
            As[kk][aa] = Yg[(a0 + aa) * CH + k0 + kk];
            Bs[kk][aa] = Vg[(b0 + aa) * CH + k0 + kk];
        }
        __syncthreads();
        #pragma unroll
        for (int k = 0; k < 32; ++k) {
            float4 av = *(const float4*)&As[k][ty * 4];
            float4 bv = *(const float4*)&Bs[k][tx * 4];
            float a[4] = {av.x, av.y, av.z, av.w};
            float b[4] = {bv.x, bv.y, bv.z, bv.w};
            #pragma unroll
            for (int i = 0; i < 4; ++i)
                #pragma unroll
                for (int j = 0; j < 4; ++j)
                    acc[i][j] += a[i] * b[j];
        }
    }
    float* Qg = g_Q + g * CH * CH;
    #pragma unroll
    for (int i = 0; i < 4; ++i) {
        int a = a0 + ty * 4 + i;
        #pragma unroll
        for (int j = 0; j < 4; ++j) {
            int b = b0 + tx * 4 + j;
            Qg[a * CH + b] = (a == b ? 1.0f : 0.0f) - acc[i][j];
        }
    }
}

// ---------------- out = x @ Q  (BM=128, BN=64, BK=32; 8x4 micro) -----------
__global__ void main_kernel(const float* __restrict__ X, float* __restrict__ out) {
    int g  = blockIdx.z;
    int m0 = blockIdx.y * 128;
    int n0 = blockIdx.x * 64;

    __shared__ float As[32][132];   // 528 B rows, 16B-aligned
    __shared__ float Bs[32][68];    // 272 B rows, 16B-aligned

    const float* Xg = X + (size_t)g * BSZ * CH;
    const float* Qg = g_Q + g * CH * CH;
    float*       Og = out + (size_t)g * BSZ * CH;

    int t = threadIdx.x;
    int ty = t >> 4, tx = t & 15;   // 16x16 threads, 8x4 micro-tile
    float acc[8][4] = {};

    for (int k0 = 0; k0 < CH; k0 += 32) {
        __syncthreads();
        // x tile: 128 m x 32 k, transposed into shared
        for (int e = t; e < 128 * 8; e += 256) {
            int mm = e >> 3, kk = (e & 7) << 2;
            float4 v = *(const float4*)&Xg[(size_t)(m0 + mm) * CH + k0 + kk];
            As[kk + 0][mm] = v.x;
            As[kk + 1][mm] = v.y;
            As[kk + 2][mm] = v.z;
            As[kk + 3][mm] = v.w;
        }
        // Q tile: 32 k x 64 n, direct
        for (int e = t; e < 32 * 16; e += 256) {
            int kk = e >> 4, nn = (e & 15) << 2;
            *(float4*)&Bs[kk][nn] = *(const float4*)&Qg[(k0 + kk) * CH + n0 + nn];
        }
        __syncthreads();
        #pragma unroll
        for (int k = 0; k < 32; ++k) {
            float4 b4 = *(const float4*)&Bs[k][tx * 4];
            float4 a0v = *(const float4*)&As[k][ty * 8];
            float4 a1v = *(const float4*)&As[k][ty * 8 + 4];
            float a[8] = {a0v.x, a0v.y, a0v.z, a0v.w, a1v.x, a1v.y, a1v.z, a1v.w};
            float b[4] = {b4.x, b4.y, b4.z, b4.w};
            #pragma unroll
            for (int i = 0; i < 8; ++i)
                #pragma unroll
                for (int j = 0; j < 4; ++j)
                    acc[i][j] += a[i] * b[j];
        }
    }
    #pragma unroll
    for (int i = 0; i < 8; ++i) {
        size_t row = (size_t)(m0 + ty * 8 + i) * CH;
        float4 v = {acc[i][0], acc[i][1], acc[i][2], acc[i][3]};
        *(float4*)&Og[row + n0 + tx * 4] = v;
    }
}

// ---------------- entry ----------------------------------------------------
extern "C" void kernel_launch(void* const* d_in, const int* in_sizes, int n_in,
                              void* d_out, int out_size) {
    const float* x = (const float*)d_in[0];
    const float* w = (const float*)d_in[1];
    // safety: x (16*8192*256) is the larger input
    if (n_in >= 2 && in_sizes[0] < in_sizes[1]) {
        const float* tmp = x; x = w; w = tmp;
    }
    float* out = (float*)d_out;

    beta_kernel<<<GRP, CH>>>(w);

    dim3 ggrid(CH / 64, CH / 64, GRP);
    g_kernel<<<ggrid, 256>>>(w);

    dim3 ygrid(CH / 32, GRP);
    y_kernel<<<ygrid, 256>>>(w);

    q_kernel<<<ggrid, 256>>>(w);

    dim3 mgrid(CH / 64, BSZ / 128, GRP);
    main_kernel<<<mgrid, 256>>>(x, out);
}

// round 4
// speedup vs baseline: 1.5771x; 1.5771x over previous
#include <cuda_runtime.h>
#include <cuda_bf16.h>
#include <cstdint>

#define GRP 16
#define BSZ 8192
#define CH  256

// ---------------- scratch (device globals; no allocation allowed) ----------
__device__ float g_G[GRP * CH * CH];           // G = V^T V
__device__ float g_Y[GRP * CH * CH];           // Y = V R^{-1}
__device__ __nv_bfloat16 g_Qhi[GRP * CH * CH]; // Q row-major bf16 hi
__device__ __nv_bfloat16 g_Qlo[GRP * CH * CH]; // Q row-major bf16 lo

__device__ __forceinline__ uint32_t smem_u32(const void* p) {
    uint32_t a;
    asm("{ .reg .u64 t; cvta.to.shared.u64 t, %1; cvt.u32.u64 %0, t; }"
        : "=r"(a) : "l"(p));
    return a;
}

#define LDSM4(r, addr)                                                      \
    asm volatile("ldmatrix.sync.aligned.m8n8.x4.shared.b16 {%0,%1,%2,%3}, [%4];" \
                 : "=r"((r)[0]), "=r"((r)[1]), "=r"((r)[2]), "=r"((r)[3])   \
                 : "r"(addr))
#define LDSM4T(r, addr)                                                     \
    asm volatile("ldmatrix.sync.aligned.m8n8.x4.trans.shared.b16 {%0,%1,%2,%3}, [%4];" \
                 : "=r"((r)[0]), "=r"((r)[1]), "=r"((r)[2]), "=r"((r)[3])   \
                 : "r"(addr))
#define MMA(c, a, b0, b1)                                                   \
    asm volatile("mma.sync.aligned.m16n8k16.row.col.f32.bf16.bf16.f32 "     \
                 "{%0,%1,%2,%3}, {%4,%5,%6,%7}, {%8,%9}, {%0,%1,%2,%3};"    \
                 : "+f"((c)[0]), "+f"((c)[1]), "+f"((c)[2]), "+f"((c)[3])   \
                 : "r"((a)[0]), "r"((a)[1]), "r"((a)[2]), "r"((a)[3]),      \
                   "r"(b0), "r"(b1))
#define CP16(dst, src)                                                      \
    asm volatile("cp.async.cg.shared.global [%0], [%1], 16;"                \
                 :: "r"(dst), "l"(src) : "memory")

// ---------------- G = V^T V  (64x64 tiles, k = rows of V) ------------------
__global__ void g_kernel(const float* __restrict__ W) {
    int g = blockIdx.z;
    int a0 = blockIdx.y * 64, b0 = blockIdx.x * 64;
    const float* Vg = W + g * CH * CH;

    __shared__ float As[32][68];
    __shared__ float Bs[32][68];

    int t = threadIdx.x;
    int ty = t >> 4, tx = t & 15;
    float acc[4][4] = {};

    for (int k0 = 0; k0 < CH; k0 += 32) {
        __syncthreads();
        for (int e = t; e < 32 * 64; e += 256) {
            int kk = e >> 6, aa = e & 63;
            As[kk][aa] = Vg[(k0 + kk) * CH + a0 + aa];
            Bs[kk][aa] = Vg[(k0 + kk) * CH + b0 + aa];
        }
        __syncthreads();
        #pragma unroll
        for (int k = 0; k < 32; ++k) {
            float4 av = *(const float4*)&As[k][ty * 4];
            float4 bv = *(const float4*)&Bs[k][tx * 4];
            float a[4] = {av.x, av.y, av.z, av.w};
            float b[4] = {bv.x, bv.y, bv.z, bv.w};
            #pragma unroll
            for (int i = 0; i < 4; ++i)
                #pragma unroll
                for (int j = 0; j < 4; ++j)
                    acc[i][j] += a[i] * b[j];
        }
    }
    float* Gg = g_G + g * CH * CH;
    #pragma unroll
    for (int i = 0; i < 4; ++i)
        #pragma unroll
        for (int j = 0; j < 4; ++j)
            Gg[(a0 + ty * 4 + i) * CH + b0 + tx * 4 + j] = acc[i][j];
}

// ---------------- Y = V R^{-1} ; R = diag(G)/2 + triu(G, 1) ----------------
__global__ void y_kernel(const float* __restrict__ W) {
    int g  = blockIdx.y;
    int r0 = blockIdx.x * 32;

    __shared__ float Ys[32][261];
    __shared__ float Gs[32][36];
    __shared__ float Gd[32][33];
    __shared__ float pre[32][33];
    __shared__ float betas[CH];

    const float* Vg = W   + g * CH * CH;
    const float* Gg = g_G + g * CH * CH;
    float*       Yg = g_Y + g * CH * CH;

    int t = threadIdx.x;            // 256 threads
    betas[t] = 2.0f / Gg[t * CH + t];
    __syncthreads();

    int r = t >> 3, q = t & 7;

    for (int kb = 0; kb < 8; ++kb) {
        int c0 = kb * 32;
        float4 v4 = *(const float4*)&Vg[(r0 + r) * CH + c0 + 4 * q];
        float acc[4] = {v4.x, v4.y, v4.z, v4.w};

        for (int jc = 0; jc < kb; ++jc) {
            int j0 = jc * 32;
            __syncthreads();
            for (int e = t; e < 32 * 32; e += 256) {
                int jj = e >> 5, c = e & 31;
                Gs[jj][c] = Gg[(j0 + jj) * CH + c0 + c];
            }
            __syncthreads();
            #pragma unroll
            for (int jj = 0; jj < 32; ++jj) {
                float yv = Ys[r][j0 + jj];
                float4 gg = *(const float4*)&Gs[jj][4 * q];
                acc[0] -= yv * gg.x;
                acc[1] -= yv * gg.y;
                acc[2] -= yv * gg.z;
                acc[3] -= yv * gg.w;
            }
        }
        pre[r][4 * q + 0] = acc[0];
        pre[r][4 * q + 1] = acc[1];
        pre[r][4 * q + 2] = acc[2];
        pre[r][4 * q + 3] = acc[3];
        for (int e = t; e < 32 * 32; e += 256) {
            int jj = e >> 5, c = e & 31;
            Gd[jj][c] = Gg[(c0 + jj) * CH + c0 + c];
        }
        __syncthreads();
        if (t < 32) {
            int rr = t;
            #pragma unroll 1
            for (int c = 0; c < 32; ++c) {
                float v = pre[rr][c];
                for (int d = 0; d < c; ++d)
                    v -= Ys[rr][c0 + d] * Gd[d][c];
                Ys[rr][c0 + c] = v * betas[c0 + c];
            }
        }
        __syncthreads();
    }
    for (int e = t; e < 32 * CH; e += 256) {
        int rr = e >> 8, cc = e & 255;
        Yg[(r0 + rr) * CH + cc] = Ys[rr][cc];
    }
}

// ---- Q = I - Y V^T, emitted row-major as bf16 hi/lo -----------------------
__global__ void q_kernel(const float* __restrict__ W) {
    int g = blockIdx.z;
    int a0 = blockIdx.y * 64, b0 = blockIdx.x * 64;   // a: row (=k), b: col (=n)
    const float* Yg = g_Y + g * CH * CH;
    const float* Vg = W   + g * CH * CH;

    __shared__ float As[32][68];
    __shared__ float Bs[32][68];

    int t = threadIdx.x;
    int ty = t >> 4, tx = t & 15;
    float acc[4][4] = {};

    for (int k0 = 0; k0 < CH; k0 += 32) {
        __syncthreads();
        for (int e = t; e < 64 * 32; e += 256) {
            int aa = e >> 5, kk = e & 31;
            As[kk][aa] = Yg[(a0 + aa) * CH + k0 + kk];
            Bs[kk][aa] = Vg[(b0 + aa) * CH + k0 + kk];
        }
        __syncthreads();
        #pragma unroll
        for (int k = 0; k < 32; ++k) {
            float4 av = *(const float4*)&As[k][ty * 4];
            float4 bv = *(const float4*)&Bs[k][tx * 4];
            float a[4] = {av.x, av.y, av.z, av.w};
            float b[4] = {bv.x, bv.y, bv.z, bv.w};
            #pragma unroll
            for (int i = 0; i < 4; ++i)
                #pragma unroll
                for (int j = 0; j < 4; ++j)
                    acc[i][j] += a[i] * b[j];
        }
    }
    #pragma unroll
    for (int i = 0; i < 4; ++i) {
        int a = a0 + ty * 4 + i;
        #pragma unroll
        for (int j = 0; j < 4; ++j) {
            int b = b0 + tx * 4 + j;
            float val = (a == b ? 1.0f : 0.0f) - acc[i][j];
            __nv_bfloat16 hi = __float2bfloat16(val);
            __nv_bfloat16 lo = __float2bfloat16(val - __bfloat162float(hi));
            size_t idx = ((size_t)g * CH + a) * CH + b;
            g_Qhi[idx] = hi;
            g_Qlo[idx] = lo;
        }
    }
}

// ---------------- out = x @ Q via mma.sync bf16 hi/lo split ----------------
// BM=128 BN=64 BK=32; 8 warps (4m x 2n), warp tile 32x32.
#define BM 128
#define BN 64
#define BK 32
#define SA_H 0u            // 128 rows x 80B
#define SA_L 10240u
#define SB_H 20480u        // 32 rows x 128B (swizzled)
#define SB_L 24576u
#define SBUF 28672u
#define SMEM_TOTAL (2u * SBUF)

__global__ void __launch_bounds__(256, 2) main_mma(const float* __restrict__ X,
                                                   float* __restrict__ out) {
    extern __shared__ __align__(1024) char sm[];
    const uint32_t sbase = smem_u32(sm);

    int t = threadIdx.x;
    int warp = t >> 5, lane = t & 31;
    int wm = warp >> 1, wn = warp & 1;
    int g = blockIdx.z;
    int m0 = blockIdx.x * BM, n0 = blockIdx.y * BN;

    const float* Xg = X + ((size_t)g * BSZ + m0) * CH;
    const __nv_bfloat16* Qh = g_Qhi + (size_t)g * CH * CH;
    const __nv_bfloat16* Ql = g_Qlo + (size_t)g * CH * CH;

    // A staging: thread t handles row ar, cols [ac, ac+16) of the 128x32 chunk
    int ar = t >> 1, ac = (t & 1) * 16;
    // B cp.async: thread t copies 16B: row bk, n-granule bg (8 bf16)
    int bk = t >> 3, bg = t & 7;
    uint32_t boff = (uint32_t)bk * 128 + (uint32_t)((bg ^ (bk & 7)) << 4);

    float acc[2][4][4] = {};
    float4 xa[4];

    auto loadA = [&](int ch) {
        #pragma unroll
        for (int i = 0; i < 4; ++i)
            xa[i] = *(const float4*)(Xg + (size_t)ar * CH + ch * BK + ac + i * 4);
    };
    auto issueB = [&](int ch) {
        uint32_t d = sbase + (uint32_t)(ch & 1) * SBUF;
        const __nv_bfloat16* sh = Qh + (size_t)(ch * BK + bk) * CH + n0 + bg * 8;
        const __nv_bfloat16* sl = Ql + (size_t)(ch * BK + bk) * CH + n0 + bg * 8;
        CP16(d + SB_H + boff, sh);
        CP16(d + SB_L + boff, sl);
        asm volatile("cp.async.commit_group;" ::: "memory");
    };
    auto storeA = [&](int ch) {
        char* p = sm + (ch & 1) * SBUF;
        float f[16] = {xa[0].x, xa[0].y, xa[0].z, xa[0].w,
                       xa[1].x, xa[1].y, xa[1].z, xa[1].w,
                       xa[2].x, xa[2].y, xa[2].z, xa[2].w,
                       xa[3].x, xa[3].y, xa[3].z, xa[3].w};
        uint32_t h[8], l[8];
        #pragma unroll
        for (int i = 0; i < 8; ++i) {
            float f0 = f[2 * i], f1 = f[2 * i + 1];
            __nv_bfloat16 h0 = __float2bfloat16(f0);
            __nv_bfloat16 h1 = __float2bfloat16(f1);
            __nv_bfloat16 l0 = __float2bfloat16(f0 - __bfloat162float(h0));
            __nv_bfloat16 l1 = __float2bfloat16(f1 - __bfloat162float(h1));
            h[i] = ((uint32_t)__bfloat16_as_ushort(h1) << 16) | __bfloat16_as_ushort(h0);
            l[i] = ((uint32_t)__bfloat16_as_ushort(l1) << 16) | __bfloat16_as_ushort(l0);
        }
        uint32_t ao = ar * 80u + ac * 2u;
        *(uint4*)(p + SA_H + ao)      = make_uint4(h[0], h[1], h[2], h[3]);
        *(uint4*)(p + SA_H + ao + 16) = make_uint4(h[4], h[5], h[6], h[7]);
        *(uint4*)(p + SA_L + ao)      = make_uint4(l[0], l[1], l[2], l[3]);
        *(uint4*)(p + SA_L + ao + 16) = make_uint4(l[4], l[5], l[6], l[7]);
    };

    loadA(0);
    issueB(0);

    for (int ch = 0; ch < CH / BK; ++ch) {
        asm volatile("cp.async.wait_group 0;" ::: "memory");
        storeA(ch);
        __syncthreads();
        if (ch + 1 < CH / BK) { loadA(ch + 1); issueB(ch + 1); }

        uint32_t sb = sbase + (uint32_t)(ch & 1) * SBUF;
        #pragma unroll
        for (int ks = 0; ks < BK; ks += 16) {
            uint32_t ah[2][4], al[2][4], bh[8], bl[8];
            // A frags: m16 tiles at wm*32 + {0,16}
            #pragma unroll
            for (int i = 0; i < 2; ++i) {
                uint32_t mrow = (uint32_t)(wm * 32 + i * 16 + (lane & 15));
                uint32_t kcol = (uint32_t)(ks + (lane >> 4) * 8);
                uint32_t addr = sb + SA_H + mrow * 80u + kcol * 2u;
                LDSM4(ah[i], addr);
                LDSM4(al[i], addr + (SA_L - SA_H));
            }
            // B frags: n16 tiles at wn*32 + {0,16} (trans), swizzled
            #pragma unroll
            for (int p = 0; p < 2; ++p) {
                uint32_t krow = (uint32_t)(ks + (lane & 15));
                uint32_t gran = (uint32_t)(wn * 4 + p * 2 + (lane >> 4));
                uint32_t addr = sb + SB_H + krow * 128u + ((gran ^ (krow & 7)) << 4);
                LDSM4T(&bh[4 * p], addr);
                LDSM4T(&bl[4 * p], addr + (SB_L - SB_H));
            }
            #pragma unroll
            for (int i = 0; i < 2; ++i)
                #pragma unroll
                for (int j = 0; j < 4; ++j) {
                    MMA(acc[i][j], ah[i], bh[2 * j], bh[2 * j + 1]);
                    MMA(acc[i][j], ah[i], bl[2 * j], bl[2 * j + 1]);
                    MMA(acc[i][j], al[i], bh[2 * j], bh[2 * j + 1]);
                }
        }
    }

    // epilogue: direct stores (float2 per fragment half-row)
    #pragma unroll
    for (int i = 0; i < 2; ++i) {
        int row = m0 + wm * 32 + i * 16 + (lane >> 2);
        float* o0 = out + ((size_t)g * BSZ + row) * CH + n0 + wn * 32 + (lane & 3) * 2;
        #pragma unroll
        for (int j = 0; j < 4; ++j) {
            *(float2*)(o0 + j * 8)          = make_float2(acc[i][j][0], acc[i][j][1]);
            *(float2*)(o0 + 8 * CH + j * 8) = make_float2(acc[i][j][2], acc[i][j][3]);
        }
    }
}

// ---------------- entry ----------------------------------------------------
extern "C" void kernel_launch(void* const* d_in, const int* in_sizes, int n_in,
                              void* d_out, int out_size) {
    const float* x = (const float*)d_in[0];
    const float* w = (const float*)d_in[1];
    if (n_in >= 2 && in_sizes[0] < in_sizes[1]) {
        const float* tmp = x; x = w; w = tmp;
    }
    float* out = (float*)d_out;

    cudaFuncSetAttribute(main_mma, cudaFuncAttributeMaxDynamicSharedMemorySize,
                         SMEM_TOTAL);

    dim3 ggrid(CH / 64, CH / 64, GRP);
    g_kernel<<<ggrid, 256>>>(w);

    dim3 ygrid(CH / 32, GRP);
    y_kernel<<<ygrid, 256>>>(w);

    q_kernel<<<ggrid, 256>>>(w);

    dim3 mgrid(BSZ / BM, CH / BN, GRP);
    main_mma<<<mgrid, 256, SMEM_TOTAL>>>(x, out);
}

// round 5
// speedup vs baseline: 1.7439x; 1.1057x over previous
#include <cuda_runtime.h>
#include <cuda_bf16.h>
#include <cstdint>

#define GRP 16
#define BSZ 8192
#define CH  256

// ---------------- scratch (device globals; no allocation allowed) ----------
__device__ float g_G[GRP * CH * CH];           // G = V^T V
__device__ float g_Y[GRP * CH * CH];           // Y = V R^{-1}
__device__ __nv_bfloat16 g_Qhi[GRP * CH * CH]; // Q row-major bf16 hi
__device__ __nv_bfloat16 g_Qlo[GRP * CH * CH]; // Q row-major bf16 lo

__device__ __forceinline__ uint32_t smem_u32(const void* p) {
    uint32_t a;
    asm("{ .reg .u64 t; cvta.to.shared.u64 t, %1; cvt.u32.u64 %0, t; }"
        : "=r"(a) : "l"(p));
    return a;
}

#define LDSM4(r, addr)                                                      \
    asm volatile("ldmatrix.sync.aligned.m8n8.x4.shared.b16 {%0,%1,%2,%3}, [%4];" \
                 : "=r"((r)[0]), "=r"((r)[1]), "=r"((r)[2]), "=r"((r)[3])   \
                 : "r"(addr))
#define LDSM4T(r, addr)                                                     \
    asm volatile("ldmatrix.sync.aligned.m8n8.x4.trans.shared.b16 {%0,%1,%2,%3}, [%4];" \
                 : "=r"((r)[0]), "=r"((r)[1]), "=r"((r)[2]), "=r"((r)[3])   \
                 : "r"(addr))
#define MMA(c, a, b0, b1)                                                   \
    asm volatile("mma.sync.aligned.m16n8k16.row.col.f32.bf16.bf16.f32 "     \
                 "{%0,%1,%2,%3}, {%4,%5,%6,%7}, {%8,%9}, {%0,%1,%2,%3};"    \
                 : "+f"((c)[0]), "+f"((c)[1]), "+f"((c)[2]), "+f"((c)[3])   \
                 : "r"((a)[0]), "r"((a)[1]), "r"((a)[2]), "r"((a)[3]),      \
                   "r"(b0), "r"(b1))
#define CP16(dst, src)                                                      \
    asm volatile("cp.async.cg.shared.global [%0], [%1], 16;"                \
                 :: "r"(dst), "l"(src) : "memory")

// ---------------- G = V^T V  (32x64 tiles for occupancy) -------------------
__global__ void g_kernel(const float* __restrict__ W) {
    int g = blockIdx.z;
    int a0 = blockIdx.y * 32, b0 = blockIdx.x * 64;
    const float* Vg = W + g * CH * CH;

    __shared__ float As[32][36];   // 32k x 32a (144B rows, aligned)
    __shared__ float Bs[32][68];   // 32k x 64b

    int t = threadIdx.x;
    int ty = t >> 4, tx = t & 15;  // 2x4 micro-tile
    float acc[2][4] = {};

    for (int k0 = 0; k0 < CH; k0 += 32) {
        __syncthreads();
        for (int e = t; e < 32 * 32; e += 256) {
            int kk = e >> 5, aa = e & 31;
            As[kk][aa] = Vg[(k0 + kk) * CH + a0 + aa];
        }
        for (int e = t; e < 32 * 64; e += 256) {
            int kk = e >> 6, bb = e & 63;
            Bs[kk][bb] = Vg[(k0 + kk) * CH + b0 + bb];
        }
        __syncthreads();
        #pragma unroll
        for (int k = 0; k < 32; ++k) {
            float2 av = *(const float2*)&As[k][ty * 2];
            float4 bv = *(const float4*)&Bs[k][tx * 4];
            float a[2] = {av.x, av.y};
            float b[4] = {bv.x, bv.y, bv.z, bv.w};
            #pragma unroll
            for (int i = 0; i < 2; ++i)
                #pragma unroll
                for (int j = 0; j < 4; ++j)
                    acc[i][j] += a[i] * b[j];
        }
    }
    float* Gg = g_G + g * CH * CH;
    #pragma unroll
    for (int i = 0; i < 2; ++i)
        #pragma unroll
        for (int j = 0; j < 4; ++j)
            Gg[(a0 + ty * 2 + i) * CH + b0 + tx * 4 + j] = acc[i][j];
}

// ---------------- Y = V R^{-1} ; R = diag(G)/2 + triu(G, 1) ----------------
__global__ void y_kernel(const float* __restrict__ W) {
    int g  = blockIdx.y;
    int r0 = blockIdx.x * 32;

    __shared__ float Ys[32][261];
    __shared__ float Gs[32][36];
    __shared__ float Gd[32][33];
    __shared__ float pre[32][33];
    __shared__ float betas[CH];

    const float* Vg = W   + g * CH * CH;
    const float* Gg = g_G + g * CH * CH;
    float*       Yg = g_Y + g * CH * CH;

    int t = threadIdx.x;            // 256 threads
    betas[t] = 2.0f / Gg[t * CH + t];
    __syncthreads();

    int r = t >> 3, q = t & 7;

    for (int kb = 0; kb < 8; ++kb) {
        int c0 = kb * 32;
        float4 v4 = *(const float4*)&Vg[(r0 + r) * CH + c0 + 4 * q];
        float acc[4] = {v4.x, v4.y, v4.z, v4.w};

        for (int jc = 0; jc < kb; ++jc) {
            int j0 = jc * 32;
            __syncthreads();
            for (int e = t; e < 32 * 32; e += 256) {
                int jj = e >> 5, c = e & 31;
                Gs[jj][c] = Gg[(j0 + jj) * CH + c0 + c];
            }
            __syncthreads();
            #pragma unroll
            for (int jj = 0; jj < 32; ++jj) {
                float yv = Ys[r][j0 + jj];
                float4 gg = *(const float4*)&Gs[jj][4 * q];
                acc[0] -= yv * gg.x;
                acc[1] -= yv * gg.y;
                acc[2] -= yv * gg.z;
                acc[3] -= yv * gg.w;
            }
        }
        pre[r][4 * q + 0] = acc[0];
        pre[r][4 * q + 1] = acc[1];
        pre[r][4 * q + 2] = acc[2];
        pre[r][4 * q + 3] = acc[3];
        for (int e = t; e < 32 * 32; e += 256) {
            int jj = e >> 5, c = e & 31;
            Gd[jj][c] = Gg[(c0 + jj) * CH + c0 + c];
        }
        __syncthreads();
        if (t < 32) {
            int rr = t;
            #pragma unroll 1
            for (int c = 0; c < 32; ++c) {
                float v = pre[rr][c];
                for (int d = 0; d < c; ++d)
                    v -= Ys[rr][c0 + d] * Gd[d][c];
                Ys[rr][c0 + c] = v * betas[c0 + c];
            }
        }
        __syncthreads();
    }
    for (int e = t; e < 32 * CH; e += 256) {
        int rr = e >> 8, cc = e & 255;
        Yg[(r0 + rr) * CH + cc] = Ys[rr][cc];
    }
}

// ---- Q = I - Y V^T, row-major bf16 hi/lo (32x64 tiles) --------------------
__global__ void q_kernel(const float* __restrict__ W) {
    int g = blockIdx.z;
    int a0 = blockIdx.y * 32, b0 = blockIdx.x * 64;   // a: row (=k), b: col (=n)
    const float* Yg = g_Y + g * CH * CH;
    const float* Vg = W   + g * CH * CH;

    __shared__ float As[32][36];   // k x 32a
    __shared__ float Bs[32][68];   // k x 64b

    int t = threadIdx.x;
    int ty = t >> 4, tx = t & 15;
    float acc[2][4] = {};

    for (int k0 = 0; k0 < CH; k0 += 32) {
        __syncthreads();
        for (int e = t; e < 32 * 32; e += 256) {
            int aa = e >> 5, kk = e & 31;
            As[kk][aa] = Yg[(a0 + aa) * CH + k0 + kk];
        }
        for (int e = t; e < 64 * 32; e += 256) {
            int bb = e >> 5, kk = e & 31;
            Bs[kk][bb] = Vg[(b0 + bb) * CH + k0 + kk];
        }
        __syncthreads();
        #pragma unroll
        for (int k = 0; k < 32; ++k) {
            float2 av = *(const float2*)&As[k][ty * 2];
            float4 bv = *(const float4*)&Bs[k][tx * 4];
            float a[2] = {av.x, av.y};
            float b[4] = {bv.x, bv.y, bv.z, bv.w};
            #pragma unroll
            for (int i = 0; i < 2; ++i)
                #pragma unroll
                for (int j = 0; j < 4; ++j)
                    acc[i][j] += a[i] * b[j];
        }
    }
    #pragma unroll
    for (int i = 0; i < 2; ++i) {
        int a = a0 + ty * 2 + i;
        #pragma unroll
        for (int j = 0; j < 4; ++j) {
            int b = b0 + tx * 4 + j;
            float val = (a == b ? 1.0f : 0.0f) - acc[i][j];
            __nv_bfloat16 hi = __float2bfloat16(val);
            __nv_bfloat16 lo = __float2bfloat16(val - __bfloat162float(hi));
            size_t idx = ((size_t)g * CH + a) * CH + b;
            g_Qhi[idx] = hi;
            g_Qlo[idx] = lo;
        }
    }
}

// ---------------- out = x @ Q via mma.sync bf16 hi/lo split ----------------
// BM=128 BN=128 BK=32; 8 warps as 2m x 4n, warp tile 64x32.
#define BM 128
#define BN 128
#define BK 32
#define SA_H 0u            // 128 rows x 80B
#define SA_L 10240u
#define SB_H 20480u        // 32 rows x 256B (swizzled 16B granules)
#define SB_L 28672u
#define SBUF 36864u
#define SMEM_TOTAL (2u * SBUF)

__global__ void __launch_bounds__(256, 2) main_mma(const float* __restrict__ X,
                                                   float* __restrict__ out) {
    extern __shared__ __align__(1024) char sm[];
    const uint32_t sbase = smem_u32(sm);

    int t = threadIdx.x;
    int warp = t >> 5, lane = t & 31;
    int wm = warp >> 2, wn = warp & 3;      // warp tile 64m x 32n
    int g = blockIdx.z;
    int m0 = blockIdx.x * BM, n0 = blockIdx.y * BN;

    const float* Xg = X + ((size_t)g * BSZ + m0) * CH;
    const __nv_bfloat16* Qh = g_Qhi + (size_t)g * CH * CH;
    const __nv_bfloat16* Ql = g_Qlo + (size_t)g * CH * CH;

    // A staging: thread t -> row ar, cols [ac, ac+16) of the 128x32 chunk
    int ar = t >> 1, ac = (t & 1) * 16;
    // B cp.async: 32 rows x 16 granules of 16B; thread covers 2 rows
    int brow = t >> 4, bgr = t & 15;

    float acc[4][4][4] = {};
    float4 xa[4];

    auto loadA = [&](int ch) {
        #pragma unroll
        for (int i = 0; i < 4; ++i)
            xa[i] = *(const float4*)(Xg + (size_t)ar * CH + ch * BK + ac + i * 4);
    };
    auto issueB = [&](int ch) {
        uint32_t d = sbase + (uint32_t)(ch & 1) * SBUF;
        #pragma unroll
        for (int r2 = 0; r2 < 2; ++r2) {
            int row = brow + r2 * 16;
            uint32_t off = (uint32_t)row * 256 + (uint32_t)((bgr ^ (row & 7)) << 4);
            const __nv_bfloat16* sh = Qh + (size_t)(ch * BK + row) * CH + n0 + bgr * 8;
            const __nv_bfloat16* sl = Ql + (size_t)(ch * BK + row) * CH + n0 + bgr * 8;
            CP16(d + SB_H + off, sh);
            CP16(d + SB_L + off, sl);
        }
        asm volatile("cp.async.commit_group;" ::: "memory");
    };
    auto storeA = [&](int ch) {
        char* p = sm + (ch & 1) * SBUF;
        float f[16] = {xa[0].x, xa[0].y, xa[0].z, xa[0].w,
                       xa[1].x, xa[1].y, xa[1].z, xa[1].w,
                       xa[2].x, xa[2].y, xa[2].z, xa[2].w,
                       xa[3].x, xa[3].y, xa[3].z, xa[3].w};
        uint32_t h[8], l[8];
        #pragma unroll
        for (int i = 0; i < 8; ++i) {
            float f0 = f[2 * i], f1 = f[2 * i + 1];
            __nv_bfloat16 h0 = __float2bfloat16(f0);
            __nv_bfloat16 h1 = __float2bfloat16(f1);
            __nv_bfloat16 l0 = __float2bfloat16(f0 - __bfloat162float(h0));
            __nv_bfloat16 l1 = __float2bfloat16(f1 - __bfloat162float(h1));
            h[i] = ((uint32_t)__bfloat16_as_ushort(h1) << 16) | __bfloat16_as_ushort(h0);
            l[i] = ((uint32_t)__bfloat16_as_ushort(l1) << 16) | __bfloat16_as_ushort(l0);
        }
        uint32_t ao = ar * 80u + ac * 2u;
        *(uint4*)(p + SA_H + ao)      = make_uint4(h[0], h[1], h[2], h[3]);
        *(uint4*)(p + SA_H + ao + 16) = make_uint4(h[4], h[5], h[6], h[7]);
        *(uint4*)(p + SA_L + ao)      = make_uint4(l[0], l[1], l[2], l[3]);
        *(uint4*)(p + SA_L + ao + 16) = make_uint4(l[4], l[5], l[6], l[7]);
    };

    loadA(0);
    issueB(0);

    for (int ch = 0; ch < CH / BK; ++ch) {
        asm volatile("cp.async.wait_group 0;" ::: "memory");
        storeA(ch);
        __syncthreads();
        if (ch + 1 < CH / BK) { loadA(ch + 1); issueB(ch + 1); }

        uint32_t sb = sbase + (uint32_t)(ch & 1) * SBUF;
        #pragma unroll
        for (int ks = 0; ks < BK; ks += 16) {
            uint32_t ah[4][4], al[4][4];
            // A frags: 4 m16 tiles at wm*64 + i*16
            #pragma unroll
            for (int i = 0; i < 4; ++i) {
                uint32_t mrow = (uint32_t)(wm * 64 + i * 16 + (lane & 15));
                uint32_t kcol = (uint32_t)(ks + (lane >> 4) * 8);
                uint32_t addr = sb + SA_H + mrow * 80u + kcol * 2u;
                LDSM4(ah[i], addr);
                LDSM4(al[i], addr + (SA_L - SA_H));
            }
            // B frags: 2 n16 tiles at wn*32 + p*16 (trans)
            #pragma unroll
            for (int p = 0; p < 2; ++p) {
                uint32_t bh[4], bl[4];
                uint32_t krow = (uint32_t)(ks + (lane & 15));
                uint32_t gran = (uint32_t)(wn * 4 + p * 2 + (lane >> 4));
                uint32_t addr = sb + SB_H + krow * 256u + ((gran ^ (krow & 7)) << 4);
                LDSM4T(bh, addr);
                LDSM4T(bl, addr + (SB_L - SB_H));
                #pragma unroll
                for (int i = 0; i < 4; ++i) {
                    MMA(acc[i][2 * p],     ah[i], bh[0], bh[1]);
                    MMA(acc[i][2 * p],     ah[i], bl[0], bl[1]);
                    MMA(acc[i][2 * p],     al[i], bh[0], bh[1]);
                    MMA(acc[i][2 * p + 1], ah[i], bh[2], bh[3]);
                    MMA(acc[i][2 * p + 1], ah[i], bl[2], bl[3]);
                    MMA(acc[i][2 * p + 1], al[i], bh[2], bh[3]);
                }
            }
        }
    }

    // epilogue
    #pragma unroll
    for (int i = 0; i < 4; ++i) {
        int row = m0 + wm * 64 + i * 16 + (lane >> 2);
        float* o0 = out + ((size_t)g * BSZ + row) * CH + n0 + wn * 32 + (lane & 3) * 2;
        #pragma unroll
        for (int j = 0; j < 4; ++j) {
            *(float2*)(o0 + j * 8)          = make_float2(acc[i][j][0], acc[i][j][1]);
            *(float2*)(o0 + 8 * CH + j * 8) = make_float2(acc[i][j][2], acc[i][j][3]);
        }
    }
}

// ---------------- entry ----------------------------------------------------
extern "C" void kernel_launch(void* const* d_in, const int* in_sizes, int n_in,
                              void* d_out, int out_size) {
    const float* x = (const float*)d_in[0];
    const float* w = (const float*)d_in[1];
    if (n_in >= 2 && in_sizes[0] < in_sizes[1]) {
        const float* tmp = x; x = w; w = tmp;
    }
    float* out = (float*)d_out;

    cudaFuncSetAttribute(main_mma, cudaFuncAttributeMaxDynamicSharedMemorySize,
                         SMEM_TOTAL);

    dim3 ggrid(CH / 64, CH / 32, GRP);   // 4 x 8 x 16 = 512 CTAs
    g_kernel<<<ggrid, 256>>>(w);

    dim3 ygrid(CH / 32, GRP);
    y_kernel<<<ygrid, 256>>>(w);

    q_kernel<<<ggrid, 256>>>(w);

    dim3 mgrid(BSZ / BM, CH / BN, GRP);  // 64 x 2 x 16 = 2048 CTAs
    main_mma<<<mgrid, 256, SMEM_TOTAL>>>(x, out);
}

// round 6
// speedup vs baseline: 2.0356x; 1.1673x over previous
#include <cuda_runtime.h>
#include <cuda_bf16.h>
#include <cstdint>

#define GRP 16
#define BSZ 8192
#define CH  256

// ---------------- scratch (device globals; no allocation allowed) ----------
__device__ float g_G[GRP * CH * CH];           // G = V^T V (upper blocks only)
__device__ float g_Y[GRP * CH * CH];           // Y = V R^{-1}
__device__ __nv_bfloat16 g_Qhi[GRP * CH * CH]; // Q row-major bf16 hi
__device__ __nv_bfloat16 g_Qlo[GRP * CH * CH]; // Q row-major bf16 lo

__device__ __forceinline__ uint32_t smem_u32(const void* p) {
    uint32_t a;
    asm("{ .reg .u64 t; cvta.to.shared.u64 t, %1; cvt.u32.u64 %0, t; }"
        : "=r"(a) : "l"(p));
    return a;
}

#define LDSM4(r, addr)                                                      \
    asm volatile("ldmatrix.sync.aligned.m8n8.x4.shared.b16 {%0,%1,%2,%3}, [%4];" \
                 : "=r"((r)[0]), "=r"((r)[1]), "=r"((r)[2]), "=r"((r)[3])   \
                 : "r"(addr))
#define LDSM4T(r, addr)                                                     \
    asm volatile("ldmatrix.sync.aligned.m8n8.x4.trans.shared.b16 {%0,%1,%2,%3}, [%4];" \
                 : "=r"((r)[0]), "=r"((r)[1]), "=r"((r)[2]), "=r"((r)[3])   \
                 : "r"(addr))
#define MMA(c, a, b0, b1)                                                   \
    asm volatile("mma.sync.aligned.m16n8k16.row.col.f32.bf16.bf16.f32 "     \
                 "{%0,%1,%2,%3}, {%4,%5,%6,%7}, {%8,%9}, {%0,%1,%2,%3};"    \
                 : "+f"((c)[0]), "+f"((c)[1]), "+f"((c)[2]), "+f"((c)[3])   \
                 : "r"((a)[0]), "r"((a)[1]), "r"((a)[2]), "r"((a)[3]),      \
                   "r"(b0), "r"(b1))
#define CP16(dst, src)                                                      \
    asm volatile("cp.async.cg.shared.global [%0], [%1], 16;"                \
                 :: "r"(dst), "l"(src) : "memory")

// ---------------- G = V^T V  (upper blocks only, 32x64 tiles) --------------
__global__ void g_kernel(const float* __restrict__ W) {
    int g = blockIdx.z;
    int a0 = blockIdx.y * 32, b0 = blockIdx.x * 64;
    if (a0 >= b0 + 64) return;          // strictly-lower block: never read
    const float* Vg = W + g * CH * CH;

    __shared__ float As[32][36];
    __shared__ float Bs[32][68];

    int t = threadIdx.x;
    int ty = t >> 4, tx = t & 15;
    float acc[2][4] = {};

    for (int k0 = 0; k0 < CH; k0 += 32) {
        __syncthreads();
        for (int e = t; e < 32 * 32; e += 256) {
            int kk = e >> 5, aa = e & 31;
            As[kk][aa] = Vg[(k0 + kk) * CH + a0 + aa];
        }
        for (int e = t; e < 32 * 64; e += 256) {
            int kk = e >> 6, bb = e & 63;
            Bs[kk][bb] = Vg[(k0 + kk) * CH + b0 + bb];
        }
        __syncthreads();
        #pragma unroll
        for (int k = 0; k < 32; ++k) {
            float2 av = *(const float2*)&As[k][ty * 2];
            float4 bv = *(const float4*)&Bs[k][tx * 4];
            float a[2] = {av.x, av.y};
            float b[4] = {bv.x, bv.y, bv.z, bv.w};
            #pragma unroll
            for (int i = 0; i < 2; ++i)
                #pragma unroll
                for (int j = 0; j < 4; ++j)
                    acc[i][j] += a[i] * b[j];
        }
    }
    float* Gg = g_G + g * CH * CH;
    #pragma unroll
    for (int i = 0; i < 2; ++i)
        #pragma unroll
        for (int j = 0; j < 4; ++j)
            Gg[(a0 + ty * 2 + i) * CH + b0 + tx * 4 + j] = acc[i][j];
}

// ---------------- Y = V R^{-1} ; R = diag(G)/2 + triu(G, 1) ----------------
__global__ void y_kernel(const float* __restrict__ W) {
    int g  = blockIdx.y;
    int r0 = blockIdx.x * 32;

    __shared__ float Ys[32][261];
    __shared__ float Gs[32][36];
    __shared__ float Gd[32][33];
    __shared__ float pre[32][33];
    __shared__ float betas[CH];

    const float* Vg = W   + g * CH * CH;
    const float* Gg = g_G + g * CH * CH;
    float*       Yg = g_Y + g * CH * CH;

    int t = threadIdx.x;            // 256 threads
    betas[t] = 2.0f / Gg[t * CH + t];
    __syncthreads();

    int r = t >> 3, q = t & 7;

    for (int kb = 0; kb < 8; ++kb) {
        int c0 = kb * 32;
        float4 v4 = *(const float4*)&Vg[(r0 + r) * CH + c0 + 4 * q];
        float acc[4] = {v4.x, v4.y, v4.z, v4.w};

        for (int jc = 0; jc < kb; ++jc) {
            int j0 = jc * 32;
            __syncthreads();
            for (int e = t; e < 32 * 32; e += 256) {
                int jj = e >> 5, c = e & 31;
                Gs[jj][c] = Gg[(j0 + jj) * CH + c0 + c];
            }
            __syncthreads();
            #pragma unroll
            for (int jj = 0; jj < 32; ++jj) {
                float yv = Ys[r][j0 + jj];
                float4 gg = *(const float4*)&Gs[jj][4 * q];
                acc[0] -= yv * gg.x;
                acc[1] -= yv * gg.y;
                acc[2] -= yv * gg.z;
                acc[3] -= yv * gg.w;
            }
        }
        pre[r][4 * q + 0] = acc[0];
        pre[r][4 * q + 1] = acc[1];
        pre[r][4 * q + 2] = acc[2];
        pre[r][4 * q + 3] = acc[3];
        for (int e = t; e < 32 * 32; e += 256) {
            int jj = e >> 5, c = e & 31;
            Gd[jj][c] = Gg[(c0 + jj) * CH + c0 + c];
        }
        __syncthreads();
        // In-block triangular solve: row-resident in registers (yloc),
        // fully unrolled so yloc stays in regs; Gd reads are warp-broadcast.
        if (t < 32) {
            int rr = t;
            float yloc[32];
            #pragma unroll
            for (int c = 0; c < 32; ++c) {
                float v = pre[rr][c];
                #pragma unroll
                for (int d = 0; d < c; ++d)
                    v -= yloc[d] * Gd[d][c];
                yloc[c] = v * betas[c0 + c];
                Ys[rr][c0 + c] = yloc[c];
            }
        }
        __syncthreads();
    }
    for (int e = t; e < 32 * CH; e += 256) {
        int rr = e >> 8, cc = e & 255;
        Yg[(r0 + rr) * CH + cc] = Ys[rr][cc];
    }
}

// ---- Q = I - Y V^T, row-major bf16 hi/lo (32x64 tiles) --------------------
__global__ void q_kernel(const float* __restrict__ W) {
    int g = blockIdx.z;
    int a0 = blockIdx.y * 32, b0 = blockIdx.x * 64;   // a: row (=k), b: col (=n)
    const float* Yg = g_Y + g * CH * CH;
    const float* Vg = W   + g * CH * CH;

    __shared__ float As[32][36];
    __shared__ float Bs[32][68];

    int t = threadIdx.x;
    int ty = t >> 4, tx = t & 15;
    float acc[2][4] = {};

    for (int k0 = 0; k0 < CH; k0 += 32) {
        __syncthreads();
        for (int e = t; e < 32 * 32; e += 256) {
            int aa = e >> 5, kk = e & 31;
            As[kk][aa] = Yg[(a0 + aa) * CH + k0 + kk];
        }
        for (int e = t; e < 64 * 32; e += 256) {
            int bb = e >> 5, kk = e & 31;
            Bs[kk][bb] = Vg[(b0 + bb) * CH + k0 + kk];
        }
        __syncthreads();
        #pragma unroll
        for (int k = 0; k < 32; ++k) {
            float2 av = *(const float2*)&As[k][ty * 2];
            float4 bv = *(const float4*)&Bs[k][tx * 4];
            float a[2] = {av.x, av.y};
            float b[4] = {bv.x, bv.y, bv.z, bv.w};
            #pragma unroll
            for (int i = 0; i < 2; ++i)
                #pragma unroll
                for (int j = 0; j < 4; ++j)
                    acc[i][j] += a[i] * b[j];
        }
    }
    #pragma unroll
    for (int i = 0; i < 2; ++i) {
        int a = a0 + ty * 2 + i;
        #pragma unroll
        for (int j = 0; j < 4; ++j) {
            int b = b0 + tx * 4 + j;
            float val = (a == b ? 1.0f : 0.0f) - acc[i][j];
            __nv_bfloat16 hi = __float2bfloat16(val);
            __nv_bfloat16 lo = __float2bfloat16(val - __bfloat162float(hi));
            size_t idx = ((size_t)g * CH + a) * CH + b;
            g_Qhi[idx] = hi;
            g_Qlo[idx] = lo;
        }
    }
}

// ---------------- out = x @ Q via mma.sync bf16 hi/lo split ----------------
// BM=128 BN=256 BK=32; 8 warps as 2m x 4n, warp tile 64x64.
#define BM 128
#define BN 256
#define BK 32
#define SA_H 0u            // 128 rows x 80B
#define SA_L 10240u
#define SB_H 20480u        // 32 rows x 512B (swizzled 16B granules)
#define SB_L 36864u
#define SBUF 53248u
#define SMEM_TOTAL (2u * SBUF)

__global__ void __launch_bounds__(256, 1) main_mma(const float* __restrict__ X,
                                                   float* __restrict__ out) {
    extern __shared__ __align__(1024) char sm[];
    const uint32_t sbase = smem_u32(sm);

    int t = threadIdx.x;
    int warp = t >> 5, lane = t & 31;
    int wm = warp >> 2, wn = warp & 3;      // warp tile 64m x 64n
    int g = blockIdx.y;
    int m0 = blockIdx.x * BM;

    const float* Xg = X + ((size_t)g * BSZ + m0) * CH;
    const __nv_bfloat16* Qh = g_Qhi + (size_t)g * CH * CH;
    const __nv_bfloat16* Ql = g_Qlo + (size_t)g * CH * CH;

    // A staging: thread t -> row ar, cols [ac, ac+16) of the 128x32 chunk
    int ar = t >> 1, ac = (t & 1) * 16;
    // B cp.async: 32 rows x 32 granules of 16B; thread covers 4 (row,gran)
    int br0 = t >> 5, bgr = t & 31;

    float acc[4][8][4] = {};
    float4 xa[4];

    auto loadA = [&](int ch) {
        #pragma unroll
        for (int i = 0; i < 4; ++i)
            xa[i] = *(const float4*)(Xg + (size_t)ar * CH + ch * BK + ac + i * 4);
    };
    auto issueB = [&](int ch) {
        uint32_t d = sbase + (uint32_t)(ch & 1) * SBUF;
        #pragma unroll
        for (int i = 0; i < 4; ++i) {
            int row = br0 + i * 8;
            uint32_t off = (uint32_t)row * 512 + (uint32_t)((bgr ^ (row & 7)) << 4);
            const __nv_bfloat16* sh = Qh + (size_t)(ch * BK + row) * CH + bgr * 8;
            const __nv_bfloat16* sl = Ql + (size_t)(ch * BK + row) * CH + bgr * 8;
            CP16(d + SB_H + off, sh);
            CP16(d + SB_L + off, sl);
        }
        asm volatile("cp.async.commit_group;" ::: "memory");
    };
    auto storeA = [&](int ch) {
        char* p = sm + (ch & 1) * SBUF;
        float f[16] = {xa[0].x, xa[0].y, xa[0].z, xa[0].w,
                       xa[1].x, xa[1].y, xa[1].z, xa[1].w,
                       xa[2].x, xa[2].y, xa[2].z, xa[2].w,
                       xa[3].x, xa[3].y, xa[3].z, xa[3].w};
        uint32_t h[8], l[8];
        #pragma unroll
        for (int i = 0; i < 8; ++i) {
            float f0 = f[2 * i], f1 = f[2 * i + 1];
            __nv_bfloat16 h0 = __float2bfloat16(f0);
            __nv_bfloat16 h1 = __float2bfloat16(f1);
            __nv_bfloat16 l0 = __float2bfloat16(f0 - __bfloat162float(h0));
            __nv_bfloat16 l1 = __float2bfloat16(f1 - __bfloat162float(h1));
            h[i] = ((uint32_t)__bfloat16_as_ushort(h1) << 16) | __bfloat16_as_ushort(h0);
            l[i] = ((uint32_t)__bfloat16_as_ushort(l1) << 16) | __bfloat16_as_ushort(l0);
        }
        uint32_t ao = ar * 80u + ac * 2u;
        *(uint4*)(p + SA_H + ao)      = make_uint4(h[0], h[1], h[2], h[3]);
        *(uint4*)(p + SA_H + ao + 16) = make_uint4(h[4], h[5], h[6], h[7]);
        *(uint4*)(p + SA_L + ao)      = make_uint4(l[0], l[1], l[2], l[3]);
        *(uint4*)(p + SA_L + ao + 16) = make_uint4(l[4], l[5], l[6], l[7]);
    };

    loadA(0);
    issueB(0);

    for (int ch = 0; ch < CH / BK; ++ch) {
        asm volatile("cp.async.wait_group 0;" ::: "memory");
        storeA(ch);
        __syncthreads();
        if (ch + 1 < CH / BK) { loadA(ch + 1); issueB(ch + 1); }

        uint32_t sb = sbase + (uint32_t)(ch & 1) * SBUF;
        #pragma unroll
        for (int ks = 0; ks < BK; ks += 16) {
            uint32_t ah[4][4], al[4][4];
            // A frags: 4 m16 tiles at wm*64 + i*16
            #pragma unroll
            for (int i = 0; i < 4; ++i) {
                uint32_t mrow = (uint32_t)(wm * 64 + i * 16 + (lane & 15));
                uint32_t kcol = (uint32_t)(ks + (lane >> 4) * 8);
                uint32_t addr = sb + SA_H + mrow * 80u + kcol * 2u;
                LDSM4(ah[i], addr);
                LDSM4(al[i], addr + (SA_L - SA_H));
            }
            // B frags: 4 n16 tiles at wn*64 + p*16 (trans)
            #pragma unroll
            for (int p = 0; p < 4; ++p) {
                uint32_t bh[4], bl[4];
                uint32_t krow = (uint32_t)(ks + (lane & 15));
                uint32_t gran = (uint32_t)(wn * 8 + p * 2 + (lane >> 4));
                uint32_t addr = sb + SB_H + krow * 512u + ((gran ^ (krow & 7)) << 4);
                LDSM4T(bh, addr);
                LDSM4T(bl, addr + (SB_L - SB_H));
                #pragma unroll
                for (int i = 0; i < 4; ++i) {
                    MMA(acc[i][2 * p],     ah[i], bh[0], bh[1]);
                    MMA(acc[i][2 * p],     ah[i], bl[0], bl[1]);
                    MMA(acc[i][2 * p],     al[i], bh[0], bh[1]);
                    MMA(acc[i][2 * p + 1], ah[i], bh[2], bh[3]);
                    MMA(acc[i][2 * p + 1], ah[i], bl[2], bl[3]);
                    MMA(acc[i][2 * p + 1], al[i], bh[2], bh[3]);
                }
            }
        }
    }

    // epilogue
    #pragma unroll
    for (int i = 0; i < 4; ++i) {
        int row = m0 + wm * 64 + i * 16 + (lane >> 2);
        float* o0 = out + ((size_t)g * BSZ + row) * CH + wn * 64 + (lane & 3) * 2;
        #pragma unroll
        for (int j = 0; j < 8; ++j) {
            *(float2*)(o0 + j * 8)          = make_float2(acc[i][j][0], acc[i][j][1]);
            *(float2*)(o0 + 8 * CH + j * 8) = make_float2(acc[i][j][2], acc[i][j][3]);
        }
    }
}

// ---------------- entry ----------------------------------------------------
extern "C" void kernel_launch(void* const* d_in, const int* in_sizes, int n_in,
                              void* d_out, int out_size) {
    const float* x = (const float*)d_in[0];
    const float* w = (const float*)d_in[1];
    if (n_in >= 2 && in_sizes[0] < in_sizes[1]) {
        const float* tmp = x; x = w; w = tmp;
    }
    float* out = (float*)d_out;

    cudaFuncSetAttribute(main_mma, cudaFuncAttributeMaxDynamicSharedMemorySize,
                         SMEM_TOTAL);

    dim3 ggrid(CH / 64, CH / 32, GRP);   // upper blocks only (early exit)
    g_kernel<<<ggrid, 256>>>(w);

    dim3 ygrid(CH / 32, GRP);
    y_kernel<<<ygrid, 256>>>(w);

    q_kernel<<<ggrid, 256>>>(w);

    dim3 mgrid(BSZ / BM, GRP);           // 64 x 16 = 1024 CTAs
    main_mma<<<mgrid, 256, SMEM_TOTAL>>>(x, out);
}

// round 7
// speedup vs baseline: 2.3398x; 1.1494x over previous
#include <cuda_runtime.h>
#include <cuda_bf16.h>
#include <cstdint>

#define GRP 16
#define BSZ 8192
#define CH  256

// ---------------- scratch (device globals; no allocation allowed) ----------
__device__ float g_G[GRP * CH * CH];            // G = V^T V (upper blocks)
__device__ __nv_bfloat16 g_Vhi[GRP * CH * CH];  // W split
__device__ __nv_bfloat16 g_Vlo[GRP * CH * CH];
__device__ __nv_bfloat16 g_Yhi[GRP * CH * CH];  // Y split
__device__ __nv_bfloat16 g_Ylo[GRP * CH * CH];
__device__ __nv_bfloat16 g_Qhi[GRP * CH * CH];  // Q split (row-major)
__device__ __nv_bfloat16 g_Qlo[GRP * CH * CH];

__device__ __forceinline__ uint32_t smem_u32(const void* p) {
    uint32_t a;
    asm("{ .reg .u64 t; cvta.to.shared.u64 t, %1; cvt.u32.u64 %0, t; }"
        : "=r"(a) : "l"(p));
    return a;
}

#define LDSM4(r, addr)                                                      \
    asm volatile("ldmatrix.sync.aligned.m8n8.x4.shared.b16 {%0,%1,%2,%3}, [%4];" \
                 : "=r"((r)[0]), "=r"((r)[1]), "=r"((r)[2]), "=r"((r)[3])   \
                 : "r"(addr))
#define LDSM4T(r, addr)                                                     \
    asm volatile("ldmatrix.sync.aligned.m8n8.x4.trans.shared.b16 {%0,%1,%2,%3}, [%4];" \
                 : "=r"((r)[0]), "=r"((r)[1]), "=r"((r)[2]), "=r"((r)[3])   \
                 : "r"(addr))
#define MMA(c, a, b0, b1)                                                   \
    asm volatile("mma.sync.aligned.m16n8k16.row.col.f32.bf16.bf16.f32 "     \
                 "{%0,%1,%2,%3}, {%4,%5,%6,%7}, {%8,%9}, {%0,%1,%2,%3};"    \
                 : "+f"((c)[0]), "+f"((c)[1]), "+f"((c)[2]), "+f"((c)[3])   \
                 : "r"((a)[0]), "r"((a)[1]), "r"((a)[2]), "r"((a)[3]),      \
                   "r"(b0), "r"(b1))
#define CP16(dst, src)                                                      \
    asm volatile("cp.async.cg.shared.global [%0], [%1], 16;"                \
                 :: "r"(dst), "l"(src) : "memory")

__device__ __forceinline__ uint32_t pack_hi(float a, float b) {
    __nv_bfloat16 x = __float2bfloat16(a), y = __float2bfloat16(b);
    return ((uint32_t)__bfloat16_as_ushort(y) << 16) | __bfloat16_as_ushort(x);
}
__device__ __forceinline__ uint32_t pack_lo(float a, float b) {
    __nv_bfloat16 x = __float2bfloat16(a), y = __float2bfloat16(b);
    __nv_bfloat16 lx = __float2bfloat16(a - __bfloat162float(x));
    __nv_bfloat16 ly = __float2bfloat16(b - __bfloat162float(y));
    return ((uint32_t)__bfloat16_as_ushort(ly) << 16) | __bfloat16_as_ushort(lx);
}

// ---------------- vsplit: W -> bf16 hi/lo ----------------------------------
__global__ void vsplit(const float* __restrict__ W) {
    int idx = (blockIdx.x * 256 + threadIdx.x) * 4;
    float4 v = *(const float4*)(W + idx);
    uint2 h, l;
    h.x = pack_hi(v.x, v.y); h.y = pack_hi(v.z, v.w);
    l.x = pack_lo(v.x, v.y); l.y = pack_lo(v.z, v.w);
    *(uint2*)&g_Vhi[idx] = h;
    *(uint2*)&g_Vlo[idx] = l;
}

// ---------------- g_mma: G = V^T V (upper 128x128 tiles, HMMA) -------------
// A[i][k=r] = V[r][i] (col-major storage -> ldmatrix.trans)
// B[j][k=r] = V[r][j] (k-major storage   -> ldmatrix.trans, as in main)
// smem chunk: 32 k-rows x 256B (128 bf16), regions AH/AL/BH/BL, dbl-buffered.
#define GSTRIDE 32768u
__global__ void __launch_bounds__(256) g_mma() {
    extern __shared__ __align__(1024) char sm[];
    const uint32_t sb = smem_u32(sm);
    int t = threadIdx.x, warp = t >> 5, lane = t & 31;
    int wm = warp >> 2, wn = warp & 3;
    int g = blockIdx.y;
    int bx = blockIdx.x;                 // 0:(0,0) 1:(0,128) 2:(128,128)
    int a0 = (bx == 2) ? 128 : 0;
    int b0 = (bx == 0) ? 0 : 128;

    const __nv_bfloat16* Vh = g_Vhi + (size_t)g * CH * CH;
    const __nv_bfloat16* Vl = g_Vlo + (size_t)g * CH * CH;

    int kk = t >> 3, g0 = t & 7;
    auto stage = [&](int chk) {
        uint32_t d = sb + (uint32_t)(chk & 1) * GSTRIDE;
        int krow = chk * 32 + kk;
        #pragma unroll
        for (int gi = 0; gi < 2; ++gi) {
            int gr = g0 + gi * 8;
            uint32_t off = (uint32_t)kk * 256 + (uint32_t)((gr ^ (kk & 7)) << 4);
            CP16(d + off,          Vh + (size_t)krow * CH + a0 + gr * 8);
            CP16(d + 8192  + off,  Vl + (size_t)krow * CH + a0 + gr * 8);
            CP16(d + 16384 + off,  Vh + (size_t)krow * CH + b0 + gr * 8);
            CP16(d + 24576 + off,  Vl + (size_t)krow * CH + b0 + gr * 8);
        }
        asm volatile("cp.async.commit_group;" ::: "memory");
    };

    float acc[4][4][4] = {};
    stage(0);
    for (int ch = 0; ch < 8; ++ch) {
        asm volatile("cp.async.wait_group 0;" ::: "memory");
        __syncthreads();
        if (ch < 7) stage(ch + 1);
        uint32_t buf = sb + (uint32_t)(ch & 1) * GSTRIDE;
        #pragma unroll
        for (int ks = 0; ks < 32; ks += 16) {
            uint32_t ah[4][4], al[4][4];
            #pragma unroll
            for (int i = 0; i < 4; ++i) {
                uint32_t mb = (uint32_t)(wm * 64 + i * 16);
                uint32_t krow = (uint32_t)(ks + (lane & 7) + ((lane >> 4) << 3));
                uint32_t gran = (mb >> 3) + ((lane >> 3) & 1);
                uint32_t addr = buf + krow * 256u + ((gran ^ (krow & 7)) << 4);
                LDSM4T(ah[i], addr);
                LDSM4T(al[i], addr + 8192);
            }
            #pragma unroll
            for (int p = 0; p < 2; ++p) {
                uint32_t bh[4], bl[4];
                uint32_t krow = (uint32_t)(ks + (lane & 15));
                uint32_t gran = (uint32_t)(wn * 4 + p * 2 + (lane >> 4));
                uint32_t addr = buf + 16384 + krow * 256u + ((gran ^ (krow & 7)) << 4);
                LDSM4T(bh, addr);
                LDSM4T(bl, addr + 8192);
                #pragma unroll
                for (int i = 0; i < 4; ++i) {
                    MMA(acc[i][2 * p],     ah[i], bh[0], bh[1]);
                    MMA(acc[i][2 * p],     ah[i], bl[0], bl[1]);
                    MMA(acc[i][2 * p],     al[i], bh[0], bh[1]);
                    MMA(acc[i][2 * p + 1], ah[i], bh[2], bh[3]);
                    MMA(acc[i][2 * p + 1], ah[i], bl[2], bl[3]);
                    MMA(acc[i][2 * p + 1], al[i], bh[2], bh[3]);
                }
            }
        }
    }
    float* Gg = g_G + (size_t)g * CH * CH;
    #pragma unroll
    for (int i = 0; i < 4; ++i) {
        int row = a0 + wm * 64 + i * 16 + (lane >> 2);
        #pragma unroll
        for (int j = 0; j < 4; ++j) {
            int col = b0 + wn * 32 + j * 8 + (lane & 3) * 2;
            *(float2*)&Gg[(size_t)row * CH + col]       = make_float2(acc[i][j][0], acc[i][j][1]);
            *(float2*)&Gg[(size_t)(row + 8) * CH + col] = make_float2(acc[i][j][2], acc[i][j][3]);
        }
    }
}

// ---------------- Y = V R^{-1} ; R = diag(G)/2 + triu(G, 1) ----------------
__global__ void y_kernel(const float* __restrict__ W) {
    int g  = blockIdx.y;
    int r0 = blockIdx.x * 32;

    __shared__ float Ys[32][261];
    __shared__ float Gs[32][36];
    __shared__ float Gd[32][33];
    __shared__ float pre[32][33];
    __shared__ float betas[CH];

    const float* Vg = W   + g * CH * CH;
    const float* Gg = g_G + g * CH * CH;

    int t = threadIdx.x;            // 256 threads
    betas[t] = 2.0f / Gg[t * CH + t];
    __syncthreads();

    int r = t >> 3, q = t & 7;

    for (int kb = 0; kb < 8; ++kb) {
        int c0 = kb * 32;
        float4 v4 = *(const float4*)&Vg[(r0 + r) * CH + c0 + 4 * q];
        float acc[4] = {v4.x, v4.y, v4.z, v4.w};

        for (int jc = 0; jc < kb; ++jc) {
            int j0 = jc * 32;
            __syncthreads();
            for (int e = t; e < 32 * 32; e += 256) {
                int jj = e >> 5, c = e & 31;
                Gs[jj][c] = Gg[(j0 + jj) * CH + c0 + c];
            }
            __syncthreads();
            #pragma unroll
            for (int jj = 0; jj < 32; ++jj) {
                float yv = Ys[r][j0 + jj];
                float4 gg = *(const float4*)&Gs[jj][4 * q];
                acc[0] -= yv * gg.x;
                acc[1] -= yv * gg.y;
                acc[2] -= yv * gg.z;
                acc[3] -= yv * gg.w;
            }
        }
        pre[r][4 * q + 0] = acc[0];
        pre[r][4 * q + 1] = acc[1];
        pre[r][4 * q + 2] = acc[2];
        pre[r][4 * q + 3] = acc[3];
        for (int e = t; e < 32 * 32; e += 256) {
            int jj = e >> 5, c = e & 31;
            Gd[jj][c] = Gg[(c0 + jj) * CH + c0 + c];
        }
        __syncthreads();
        // In-block solve, register-resident row, 2-way split dependent chain
        if (t < 32) {
            int rr = t;
            float yloc[32];
            #pragma unroll
            for (int c = 0; c < 32; ++c) {
                float s0 = 0.f, s1 = 0.f;
                #pragma unroll
                for (int d = 0; d + 1 < c; d += 2) {
                    s0 += yloc[d] * Gd[d][c];
                    s1 += yloc[d + 1] * Gd[d + 1][c];
                }
                if (c & 1) s0 += yloc[c - 1] * Gd[c - 1][c];
                yloc[c] = (pre[rr][c] - s0 - s1) * betas[c0 + c];
                Ys[rr][c0 + c] = yloc[c];
            }
        }
        __syncthreads();
    }
    // emit Y as bf16 hi/lo
    for (int e = t; e < 32 * (CH / 2); e += 256) {
        int rr = e >> 7, cc = (e & 127) * 2;
        float v0 = Ys[rr][cc], v1 = Ys[rr][cc + 1];
        size_t idx = ((size_t)g * CH + r0 + rr) * CH + cc;
        *(uint32_t*)&g_Yhi[idx] = pack_hi(v0, v1);
        *(uint32_t*)&g_Ylo[idx] = pack_lo(v0, v1);
    }
}

// ---------------- q_mma: Q = I - Y V^T (128x128 tiles, HMMA) ---------------
// A[a][k=i] = Y[a][i] row-major -> ldmatrix (non-trans)
// B[b][k=i] = V[b][i] row-major -> ldmatrix (non-trans), [n][k] storage
// smem chunk: 128 rows x 64B (32 bf16 of k), regions YH/YL/VH/VL.
#define QSTRIDE 32768u
__global__ void __launch_bounds__(256) q_mma() {
    extern __shared__ __align__(1024) char sm[];
    const uint32_t sb = smem_u32(sm);
    int t = threadIdx.x, warp = t >> 5, lane = t & 31;
    int wm = warp >> 2, wn = warp & 3;
    int g = blockIdx.y;
    int a0 = (blockIdx.x >> 1) * 128, b0 = (blockIdx.x & 1) * 128;

    const __nv_bfloat16* Yh = g_Yhi + (size_t)g * CH * CH;
    const __nv_bfloat16* Yl = g_Ylo + (size_t)g * CH * CH;
    const __nv_bfloat16* Vh = g_Vhi + (size_t)g * CH * CH;
    const __nv_bfloat16* Vl = g_Vlo + (size_t)g * CH * CH;

    int row = t >> 1, gp = (t & 1) * 2;
    auto stage = [&](int chk) {
        uint32_t d = sb + (uint32_t)(chk & 1) * QSTRIDE;
        int k0 = chk * 32;
        #pragma unroll
        for (int gi = 0; gi < 2; ++gi) {
            int gr = gp + gi;
            uint32_t off = (uint32_t)row * 64 + (uint32_t)((gr ^ ((row >> 1) & 3)) << 4);
            CP16(d + off,          Yh + (size_t)(a0 + row) * CH + k0 + gr * 8);
            CP16(d + 8192  + off,  Yl + (size_t)(a0 + row) * CH + k0 + gr * 8);
            CP16(d + 16384 + off,  Vh + (size_t)(b0 + row) * CH + k0 + gr * 8);
            CP16(d + 24576 + off,  Vl + (size_t)(b0 + row) * CH + k0 + gr * 8);
        }
        asm volatile("cp.async.commit_group;" ::: "memory");
    };

    float acc[4][4][4] = {};
    stage(0);
    for (int ch = 0; ch < 8; ++ch) {
        asm volatile("cp.async.wait_group 0;" ::: "memory");
        __syncthreads();
        if (ch < 7) stage(ch + 1);
        uint32_t buf = sb + (uint32_t)(ch & 1) * QSTRIDE;
        #pragma unroll
        for (int ks = 0; ks < 32; ks += 16) {
            uint32_t ah[4][4], al[4][4];
            #pragma unroll
            for (int i = 0; i < 4; ++i) {
                uint32_t mrow = (uint32_t)(wm * 64 + i * 16 + (lane & 15));
                uint32_t gran = (uint32_t)((ks >> 3) + (lane >> 4));
                uint32_t addr = buf + mrow * 64u + ((gran ^ ((mrow >> 1) & 3)) << 4);
                LDSM4(ah[i], addr);
                LDSM4(al[i], addr + 8192);
            }
            #pragma unroll
            for (int p = 0; p < 2; ++p) {
                uint32_t bh[4], bl[4];
                uint32_t nrow = (uint32_t)(wn * 32 + p * 16 + (lane & 7) + ((lane >> 4) << 3));
                uint32_t gran = (uint32_t)((ks >> 3) + ((lane >> 3) & 1));
                uint32_t addr = buf + 16384 + nrow * 64u + ((gran ^ ((nrow >> 1) & 3)) << 4);
                LDSM4(bh, addr);
                LDSM4(bl, addr + 8192);
                #pragma unroll
                for (int i = 0; i < 4; ++i) {
                    MMA(acc[i][2 * p],     ah[i], bh[0], bh[1]);
                    MMA(acc[i][2 * p],     ah[i], bl[0], bl[1]);
                    MMA(acc[i][2 * p],     al[i], bh[0], bh[1]);
                    MMA(acc[i][2 * p + 1], ah[i], bh[2], bh[3]);
                    MMA(acc[i][2 * p + 1], ah[i], bl[2], bl[3]);
                    MMA(acc[i][2 * p + 1], al[i], bh[2], bh[3]);
                }
            }
        }
    }
    #pragma unroll
    for (int i = 0; i < 4; ++i) {
        int rr = a0 + wm * 64 + i * 16 + (lane >> 2);
        #pragma unroll
        for (int j = 0; j < 4; ++j) {
            int cc = b0 + wn * 32 + j * 8 + (lane & 3) * 2;
            float v0 = (rr == cc     ? 1.f : 0.f) - acc[i][j][0];
            float v1 = (rr == cc + 1 ? 1.f : 0.f) - acc[i][j][1];
            float v2 = (rr + 8 == cc     ? 1.f : 0.f) - acc[i][j][2];
            float v3 = (rr + 8 == cc + 1 ? 1.f : 0.f) - acc[i][j][3];
            size_t i0 = ((size_t)g * CH + rr) * CH + cc;
            size_t i1 = ((size_t)g * CH + rr + 8) * CH + cc;
            *(uint32_t*)&g_Qhi[i0] = pack_hi(v0, v1);
            *(uint32_t*)&g_Qlo[i0] = pack_lo(v0, v1);
            *(uint32_t*)&g_Qhi[i1] = pack_hi(v2, v3);
            *(uint32_t*)&g_Qlo[i1] = pack_lo(v2, v3);
        }
    }
}

// ---------------- out = x @ Q via mma.sync bf16 hi/lo split ----------------
// BM=128 BN=256 BK=32; 8 warps as 2m x 4n, warp tile 64x64. (unchanged R6)
#define BM 128
#define BN 256
#define BK 32
#define SA_H 0u
#define SA_L 10240u
#define SB_H 20480u
#define SB_L 36864u
#define SBUF 53248u
#define SMEM_TOTAL (2u * SBUF)

__global__ void __launch_bounds__(256, 1) main_mma(const float* __restrict__ X,
                                                   float* __restrict__ out) {
    extern __shared__ __align__(1024) char sm[];
    const uint32_t sbase = smem_u32(sm);

    int t = threadIdx.x;
    int warp = t >> 5, lane = t & 31;
    int wm = warp >> 2, wn = warp & 3;
    int g = blockIdx.y;
    int m0 = blockIdx.x * BM;

    const float* Xg = X + ((size_t)g * BSZ + m0) * CH;
    const __nv_bfloat16* Qh = g_Qhi + (size_t)g * CH * CH;
    const __nv_bfloat16* Ql = g_Qlo + (size_t)g * CH * CH;

    int ar = t >> 1, ac = (t & 1) * 16;
    int br0 = t >> 5, bgr = t & 31;

    float acc[4][8][4] = {};
    float4 xa[4];

    auto loadA = [&](int ch) {
        #pragma unroll
        for (int i = 0; i < 4; ++i)
            xa[i] = *(const float4*)(Xg + (size_t)ar * CH + ch * BK + ac + i * 4);
    };
    auto issueB = [&](int ch) {
        uint32_t d = sbase + (uint32_t)(ch & 1) * SBUF;
        #pragma unroll
        for (int i = 0; i < 4; ++i) {
            int row = br0 + i * 8;
            uint32_t off = (uint32_t)row * 512 + (uint32_t)((bgr ^ (row & 7)) << 4);
            const __nv_bfloat16* sh = Qh + (size_t)(ch * BK + row) * CH + bgr * 8;
            const __nv_bfloat16* sl = Ql + (size_t)(ch * BK + row) * CH + bgr * 8;
            CP16(d + SB_H + off, sh);
            CP16(d + SB_L + off, sl);
        }
        asm volatile("cp.async.commit_group;" ::: "memory");
    };
    auto storeA = [&](int ch) {
        char* p = sm + (ch & 1) * SBUF;
        float f[16] = {xa[0].x, xa[0].y, xa[0].z, xa[0].w,
                       xa[1].x, xa[1].y, xa[1].z, xa[1].w,
                       xa[2].x, xa[2].y, xa[2].z, xa[2].w,
                       xa[3].x, xa[3].y, xa[3].z, xa[3].w};
        uint32_t h[8], l[8];
        #pragma unroll
        for (int i = 0; i < 8; ++i) {
            h[i] = pack_hi(f[2 * i], f[2 * i + 1]);
            l[i] = pack_lo(f[2 * i], f[2 * i + 1]);
        }
        uint32_t ao = ar * 80u + ac * 2u;
        *(uint4*)(p + SA_H + ao)      = make_uint4(h[0], h[1], h[2], h[3]);
        *(uint4*)(p + SA_H + ao + 16) = make_uint4(h[4], h[5], h[6], h[7]);
        *(uint4*)(p + SA_L + ao)      = make_uint4(l[0], l[1], l[2], l[3]);
        *(uint4*)(p + SA_L + ao + 16) = make_uint4(l[4], l[5], l[6], l[7]);
    };

    loadA(0);
    issueB(0);

    for (int ch = 0; ch < CH / BK; ++ch) {
        asm volatile("cp.async.wait_group 0;" ::: "memory");
        storeA(ch);
        __syncthreads();
        if (ch + 1 < CH / BK) { loadA(ch + 1); issueB(ch + 1); }

        uint32_t sb = sbase + (uint32_t)(ch & 1) * SBUF;
        #pragma unroll
        for (int ks = 0; ks < BK; ks += 16) {
            uint32_t ah[4][4], al[4][4];
            #pragma unroll
            for (int i = 0; i < 4; ++i) {
                uint32_t mrow = (uint32_t)(wm * 64 + i * 16 + (lane & 15));
                uint32_t kcol = (uint32_t)(ks + (lane >> 4) * 8);
                uint32_t addr = sb + SA_H + mrow * 80u + kcol * 2u;
                LDSM4(ah[i], addr);
                LDSM4(al[i], addr + (SA_L - SA_H));
            }
            #pragma unroll
            for (int p = 0; p < 4; ++p) {
                uint32_t bh[4], bl[4];
                uint32_t krow = (uint32_t)(ks + (lane & 15));
                uint32_t gran = (uint32_t)(wn * 8 + p * 2 + (lane >> 4));
                uint32_t addr = sb + SB_H + krow * 512u + ((gran ^ (krow & 7)) << 4);
                LDSM4T(bh, addr);
                LDSM4T(bl, addr + (SB_L - SB_H));
                #pragma unroll
                for (int i = 0; i < 4; ++i) {
                    MMA(acc[i][2 * p],     ah[i], bh[0], bh[1]);
                    MMA(acc[i][2 * p],     ah[i], bl[0], bl[1]);
                    MMA(acc[i][2 * p],     al[i], bh[0], bh[1]);
                    MMA(acc[i][2 * p + 1], ah[i], bh[2], bh[3]);
                    MMA(acc[i][2 * p + 1], ah[i], bl[2], bl[3]);
                    MMA(acc[i][2 * p + 1], al[i], bh[2], bh[3]);
                }
            }
        }
    }

    #pragma unroll
    for (int i = 0; i < 4; ++i) {
        int row = m0 + wm * 64 + i * 16 + (lane >> 2);
        float* o0 = out + ((size_t)g * BSZ + row) * CH + wn * 64 + (lane & 3) * 2;
        #pragma unroll
        for (int j = 0; j < 8; ++j) {
            *(float2*)(o0 + j * 8)          = make_float2(acc[i][j][0], acc[i][j][1]);
            *(float2*)(o0 + 8 * CH + j * 8) = make_float2(acc[i][j][2], acc[i][j][3]);
        }
    }
}

// ---------------- entry ----------------------------------------------------
extern "C" void kernel_launch(void* const* d_in, const int* in_sizes, int n_in,
                              void* d_out, int out_size) {
    const float* x = (const float*)d_in[0];
    const float* w = (const float*)d_in[1];
    if (n_in >= 2 && in_sizes[0] < in_sizes[1]) {
        const float* tmp = x; x = w; w = tmp;
    }
    float* out = (float*)d_out;

    cudaFuncSetAttribute(main_mma, cudaFuncAttributeMaxDynamicSharedMemorySize,
                         SMEM_TOTAL);
    cudaFuncSetAttribute(g_mma, cudaFuncAttributeMaxDynamicSharedMemorySize, 65536);
    cudaFuncSetAttribute(q_mma, cudaFuncAttributeMaxDynamicSharedMemorySize, 65536);

    vsplit<<<GRP * CH * CH / 1024, 256>>>(w);

    dim3 ggrid(3, GRP);
    g_mma<<<ggrid, 256, 65536>>>();

    dim3 ygrid(CH / 32, GRP);
    y_kernel<<<ygrid, 256>>>(w);

    dim3 qgrid(4, GRP);
    q_mma<<<qgrid, 256, 65536>>>();

    dim3 mgrid(BSZ / BM, GRP);
    main_mma<<<mgrid, 256, SMEM_TOTAL>>>(x, out);
}

// round 8
// speedup vs baseline: 2.4398x; 1.0427x over previous
#include <cuda_runtime.h>
#include <cuda_bf16.h>
#include <cstdint>

#define GRP 16
#define BSZ 8192
#define CH  256

// ---------------- scratch (device globals; no allocation allowed) ----------
__device__ float g_G[GRP * CH * CH];            // G = V^T V (upper blocks)
__device__ __nv_bfloat16 g_Vhi[GRP * CH * CH];  // W split
__device__ __nv_bfloat16 g_Vlo[GRP * CH * CH];
__device__ __nv_bfloat16 g_Yhi[GRP * CH * CH];  // Y split
__device__ __nv_bfloat16 g_Ylo[GRP * CH * CH];
__device__ __nv_bfloat16 g_Qhi[GRP * CH * CH];  // Q split (row-major)
__device__ __nv_bfloat16 g_Qlo[GRP * CH * CH];

__device__ __forceinline__ uint32_t smem_u32(const void* p) {
    uint32_t a;
    asm("{ .reg .u64 t; cvta.to.shared.u64 t, %1; cvt.u32.u64 %0, t; }"
        : "=r"(a) : "l"(p));
    return a;
}

#define LDSM4(r, addr)                                                      \
    asm volatile("ldmatrix.sync.aligned.m8n8.x4.shared.b16 {%0,%1,%2,%3}, [%4];" \
                 : "=r"((r)[0]), "=r"((r)[1]), "=r"((r)[2]), "=r"((r)[3])   \
                 : "r"(addr))
#define LDSM4T(r, addr)                                                     \
    asm volatile("ldmatrix.sync.aligned.m8n8.x4.trans.shared.b16 {%0,%1,%2,%3}, [%4];" \
                 : "=r"((r)[0]), "=r"((r)[1]), "=r"((r)[2]), "=r"((r)[3])   \
                 : "r"(addr))
#define MMA(c, a, b0, b1)                                                   \
    asm volatile("mma.sync.aligned.m16n8k16.row.col.f32.bf16.bf16.f32 "     \
                 "{%0,%1,%2,%3}, {%4,%5,%6,%7}, {%8,%9}, {%0,%1,%2,%3};"    \
                 : "+f"((c)[0]), "+f"((c)[1]), "+f"((c)[2]), "+f"((c)[3])   \
                 : "r"((a)[0]), "r"((a)[1]), "r"((a)[2]), "r"((a)[3]),      \
                   "r"(b0), "r"(b1))
#define CP16(dst, src)                                                      \
    asm volatile("cp.async.cg.shared.global [%0], [%1], 16;"                \
                 :: "r"(dst), "l"(src) : "memory")

__device__ __forceinline__ uint32_t pack_hi(float a, float b) {
    __nv_bfloat16 x = __float2bfloat16(a), y = __float2bfloat16(b);
    return ((uint32_t)__bfloat16_as_ushort(y) << 16) | __bfloat16_as_ushort(x);
}
__device__ __forceinline__ uint32_t pack_lo(float a, float b) {
    __nv_bfloat16 x = __float2bfloat16(a), y = __float2bfloat16(b);
    __nv_bfloat16 lx = __float2bfloat16(a - __bfloat162float(x));
    __nv_bfloat16 ly = __float2bfloat16(b - __bfloat162float(y));
    return ((uint32_t)__bfloat16_as_ushort(ly) << 16) | __bfloat16_as_ushort(lx);
}

// ---------------- vsplit: W -> bf16 hi/lo ----------------------------------
__global__ void vsplit(const float* __restrict__ W) {
    int idx = (blockIdx.x * 256 + threadIdx.x) * 4;
    float4 v = *(const float4*)(W + idx);
    uint2 h, l;
    h.x = pack_hi(v.x, v.y); h.y = pack_hi(v.z, v.w);
    l.x = pack_lo(v.x, v.y); l.y = pack_lo(v.z, v.w);
    *(uint2*)&g_Vhi[idx] = h;
    *(uint2*)&g_Vlo[idx] = l;
}

// ---------------- g_mma: G = V^T V (upper 128x128 tiles, HMMA) -------------
#define GSTRIDE 32768u
__global__ void __launch_bounds__(256) g_mma() {
    extern __shared__ __align__(1024) char sm[];
    const uint32_t sb = smem_u32(sm);
    int t = threadIdx.x, warp = t >> 5, lane = t & 31;
    int wm = warp >> 2, wn = warp & 3;
    int g = blockIdx.y;
    int bx = blockIdx.x;                 // 0:(0,0) 1:(0,128) 2:(128,128)
    int a0 = (bx == 2) ? 128 : 0;
    int b0 = (bx == 0) ? 0 : 128;

    const __nv_bfloat16* Vh = g_Vhi + (size_t)g * CH * CH;
    const __nv_bfloat16* Vl = g_Vlo + (size_t)g * CH * CH;

    int kk = t >> 3, g0 = t & 7;
    auto stage = [&](int chk) {
        uint32_t d = sb + (uint32_t)(chk & 1) * GSTRIDE;
        int krow = chk * 32 + kk;
        #pragma unroll
        for (int gi = 0; gi < 2; ++gi) {
            int gr = g0 + gi * 8;
            uint32_t off = (uint32_t)kk * 256 + (uint32_t)((gr ^ (kk & 7)) << 4);
            CP16(d + off,          Vh + (size_t)krow * CH + a0 + gr * 8);
            CP16(d + 8192  + off,  Vl + (size_t)krow * CH + a0 + gr * 8);
            CP16(d + 16384 + off,  Vh + (size_t)krow * CH + b0 + gr * 8);
            CP16(d + 24576 + off,  Vl + (size_t)krow * CH + b0 + gr * 8);
        }
        asm volatile("cp.async.commit_group;" ::: "memory");
    };

    float acc[4][4][4] = {};
    stage(0);
    for (int ch = 0; ch < 8; ++ch) {
        asm volatile("cp.async.wait_group 0;" ::: "memory");
        __syncthreads();
        if (ch < 7) stage(ch + 1);
        uint32_t buf = sb + (uint32_t)(ch & 1) * GSTRIDE;
        #pragma unroll
        for (int ks = 0; ks < 32; ks += 16) {
            uint32_t ah[4][4], al[4][4];
            #pragma unroll
            for (int i = 0; i < 4; ++i) {
                uint32_t mb = (uint32_t)(wm * 64 + i * 16);
                uint32_t krow = (uint32_t)(ks + (lane & 7) + ((lane >> 4) << 3));
                uint32_t gran = (mb >> 3) + ((lane >> 3) & 1);
                uint32_t addr = buf + krow * 256u + ((gran ^ (krow & 7)) << 4);
                LDSM4T(ah[i], addr);
                LDSM4T(al[i], addr + 8192);
            }
            #pragma unroll
            for (int p = 0; p < 2; ++p) {
                uint32_t bh[4], bl[4];
                uint32_t krow = (uint32_t)(ks + (lane & 15));
                uint32_t gran = (uint32_t)(wn * 4 + p * 2 + (lane >> 4));
                uint32_t addr = buf + 16384 + krow * 256u + ((gran ^ (krow & 7)) << 4);
                LDSM4T(bh, addr);
                LDSM4T(bl, addr + 8192);
                #pragma unroll
                for (int i = 0; i < 4; ++i) {
                    MMA(acc[i][2 * p],     ah[i], bh[0], bh[1]);
                    MMA(acc[i][2 * p],     ah[i], bl[0], bl[1]);
                    MMA(acc[i][2 * p],     al[i], bh[0], bh[1]);
                    MMA(acc[i][2 * p + 1], ah[i], bh[2], bh[3]);
                    MMA(acc[i][2 * p + 1], ah[i], bl[2], bl[3]);
                    MMA(acc[i][2 * p + 1], al[i], bh[2], bh[3]);
                }
            }
        }
    }
    float* Gg = g_G + (size_t)g * CH * CH;
    #pragma unroll
    for (int i = 0; i < 4; ++i) {
        int row = a0 + wm * 64 + i * 16 + (lane >> 2);
        #pragma unroll
        for (int j = 0; j < 4; ++j) {
            int col = b0 + wn * 32 + j * 8 + (lane & 3) * 2;
            *(float2*)&Gg[(size_t)row * CH + col]       = make_float2(acc[i][j][0], acc[i][j][1]);
            *(float2*)&Gg[(size_t)(row + 8) * CH + col] = make_float2(acc[i][j][2], acc[i][j][3]);
        }
    }
}

// ---------------- Y = V R^{-1} ; R = diag(G)/2 + triu(G, 1) ----------------
__global__ void y_kernel(const float* __restrict__ W) {
    int g  = blockIdx.y;
    int r0 = blockIdx.x * 32;

    __shared__ float Ys[32][261];
    __shared__ float Gs[32][36];
    __shared__ float Gd[32][33];
    __shared__ float pre[32][33];
    __shared__ float betas[CH];

    const float* Vg = W   + g * CH * CH;
    const float* Gg = g_G + g * CH * CH;

    int t = threadIdx.x;            // 256 threads
    betas[t] = 2.0f / Gg[t * CH + t];
    __syncthreads();

    int r = t >> 3, q = t & 7;

    for (int kb = 0; kb < 8; ++kb) {
        int c0 = kb * 32;
        float4 v4 = *(const float4*)&Vg[(r0 + r) * CH + c0 + 4 * q];
        float acc[4] = {v4.x, v4.y, v4.z, v4.w};

        for (int jc = 0; jc < kb; ++jc) {
            int j0 = jc * 32;
            __syncthreads();
            for (int e = t; e < 32 * 32; e += 256) {
                int jj = e >> 5, c = e & 31;
                Gs[jj][c] = Gg[(j0 + jj) * CH + c0 + c];
            }
            __syncthreads();
            #pragma unroll
            for (int jj = 0; jj < 32; ++jj) {
                float yv = Ys[r][j0 + jj];
                float4 gg = *(const float4*)&Gs[jj][4 * q];
                acc[0] -= yv * gg.x;
                acc[1] -= yv * gg.y;
                acc[2] -= yv * gg.z;
                acc[3] -= yv * gg.w;
            }
        }
        pre[r][4 * q + 0] = acc[0];
        pre[r][4 * q + 1] = acc[1];
        pre[r][4 * q + 2] = acc[2];
        pre[r][4 * q + 3] = acc[3];
        for (int e = t; e < 32 * 32; e += 256) {
            int jj = e >> 5, c = e & 31;
            Gd[jj][c] = Gg[(c0 + jj) * CH + c0 + c];
        }
        __syncthreads();
        if (t < 32) {
            int rr = t;
            float yloc[32];
            #pragma unroll
            for (int c = 0; c < 32; ++c) {
                float s0 = 0.f, s1 = 0.f;
                #pragma unroll
                for (int d = 0; d + 1 < c; d += 2) {
                    s0 += yloc[d] * Gd[d][c];
                    s1 += yloc[d + 1] * Gd[d + 1][c];
                }
                if (c & 1) s0 += yloc[c - 1] * Gd[c - 1][c];
                yloc[c] = (pre[rr][c] - s0 - s1) * betas[c0 + c];
                Ys[rr][c0 + c] = yloc[c];
            }
        }
        __syncthreads();
    }
    for (int e = t; e < 32 * (CH / 2); e += 256) {
        int rr = e >> 7, cc = (e & 127) * 2;
        float v0 = Ys[rr][cc], v1 = Ys[rr][cc + 1];
        size_t idx = ((size_t)g * CH + r0 + rr) * CH + cc;
        *(uint32_t*)&g_Yhi[idx] = pack_hi(v0, v1);
        *(uint32_t*)&g_Ylo[idx] = pack_lo(v0, v1);
    }
}

// ---------------- q_mma: Q = I - Y V^T (128x128 tiles, HMMA) ---------------
#define QSTRIDE 32768u
__global__ void __launch_bounds__(256) q_mma() {
    extern __shared__ __align__(1024) char sm[];
    const uint32_t sb = smem_u32(sm);
    int t = threadIdx.x, warp = t >> 5, lane = t & 31;
    int wm = warp >> 2, wn = warp & 3;
    int g = blockIdx.y;
    int a0 = (blockIdx.x >> 1) * 128, b0 = (blockIdx.x & 1) * 128;

    const __nv_bfloat16* Yh = g_Yhi + (size_t)g * CH * CH;
    const __nv_bfloat16* Yl = g_Ylo + (size_t)g * CH * CH;
    const __nv_bfloat16* Vh = g_Vhi + (size_t)g * CH * CH;
    const __nv_bfloat16* Vl = g_Vlo + (size_t)g * CH * CH;

    int row = t >> 1, gp = (t & 1) * 2;
    auto stage = [&](int chk) {
        uint32_t d = sb + (uint32_t)(chk & 1) * QSTRIDE;
        int k0 = chk * 32;
        #pragma unroll
        for (int gi = 0; gi < 2; ++gi) {
            int gr = gp + gi;
            uint32_t off = (uint32_t)row * 64 + (uint32_t)((gr ^ ((row >> 1) & 3)) << 4);
            CP16(d + off,          Yh + (size_t)(a0 + row) * CH + k0 + gr * 8);
            CP16(d + 8192  + off,  Yl + (size_t)(a0 + row) * CH + k0 + gr * 8);
            CP16(d + 16384 + off,  Vh + (size_t)(b0 + row) * CH + k0 + gr * 8);
            CP16(d + 24576 + off,  Vl + (size_t)(b0 + row) * CH + k0 + gr * 8);
        }
        asm volatile("cp.async.commit_group;" ::: "memory");
    };

    float acc[4][4][4] = {};
    stage(0);
    for (int ch = 0; ch < 8; ++ch) {
        asm volatile("cp.async.wait_group 0;" ::: "memory");
        __syncthreads();
        if (ch < 7) stage(ch + 1);
        uint32_t buf = sb + (uint32_t)(ch & 1) * QSTRIDE;
        #pragma unroll
        for (int ks = 0; ks < 32; ks += 16) {
            uint32_t ah[4][4], al[4][4];
            #pragma unroll
            for (int i = 0; i < 4; ++i) {
                uint32_t mrow = (uint32_t)(wm * 64 + i * 16 + (lane & 15));
                uint32_t gran = (uint32_t)((ks >> 3) + (lane >> 4));
                uint32_t addr = buf + mrow * 64u + ((gran ^ ((mrow >> 1) & 3)) << 4);
                LDSM4(ah[i], addr);
                LDSM4(al[i], addr + 8192);
            }
            #pragma unroll
            for (int p = 0; p < 2; ++p) {
                uint32_t bh[4], bl[4];
                uint32_t nrow = (uint32_t)(wn * 32 + p * 16 + (lane & 7) + ((lane >> 4) << 3));
                uint32_t gran = (uint32_t)((ks >> 3) + ((lane >> 3) & 1));
                uint32_t addr = buf + 16384 + nrow * 64u + ((gran ^ ((nrow >> 1) & 3)) << 4);
                LDSM4(bh, addr);
                LDSM4(bl, addr + 8192);
                #pragma unroll
                for (int i = 0; i < 4; ++i) {
                    MMA(acc[i][2 * p],     ah[i], bh[0], bh[1]);
                    MMA(acc[i][2 * p],     ah[i], bl[0], bl[1]);
                    MMA(acc[i][2 * p],     al[i], bh[0], bh[1]);
                    MMA(acc[i][2 * p + 1], ah[i], bh[2], bh[3]);
                    MMA(acc[i][2 * p + 1], ah[i], bl[2], bl[3]);
                    MMA(acc[i][2 * p + 1], al[i], bh[2], bh[3]);
                }
            }
        }
    }
    #pragma unroll
    for (int i = 0; i < 4; ++i) {
        int rr = a0 + wm * 64 + i * 16 + (lane >> 2);
        #pragma unroll
        for (int j = 0; j < 4; ++j) {
            int cc = b0 + wn * 32 + j * 8 + (lane & 3) * 2;
            float v0 = (rr == cc     ? 1.f : 0.f) - acc[i][j][0];
            float v1 = (rr == cc + 1 ? 1.f : 0.f) - acc[i][j][1];
            float v2 = (rr + 8 == cc     ? 1.f : 0.f) - acc[i][j][2];
            float v3 = (rr + 8 == cc + 1 ? 1.f : 0.f) - acc[i][j][3];
            size_t i0 = ((size_t)g * CH + rr) * CH + cc;
            size_t i1 = ((size_t)g * CH + rr + 8) * CH + cc;
            *(uint32_t*)&g_Qhi[i0] = pack_hi(v0, v1);
            *(uint32_t*)&g_Qlo[i0] = pack_lo(v0, v1);
            *(uint32_t*)&g_Qhi[i1] = pack_hi(v2, v3);
            *(uint32_t*)&g_Qlo[i1] = pack_lo(v2, v3);
        }
    }
}

// ---------------- out = x @ Q via mma.sync bf16 hi/lo split ----------------
// BM=128 BN=256 BK=32; 512 threads, 16 warps as 2m x 8n, warp tile 64x32.
#define BM 128
#define BN 256
#define BK 32
#define SA_H 0u
#define SA_L 10240u
#define SB_H 20480u
#define SB_L 36864u
#define SBUF 53248u
#define SMEM_TOTAL (2u * SBUF)

__global__ void __launch_bounds__(512, 1) main_mma(const float* __restrict__ X,
                                                   float* __restrict__ out) {
    extern __shared__ __align__(1024) char sm[];
    const uint32_t sbase = smem_u32(sm);

    int t = threadIdx.x;
    int warp = t >> 5, lane = t & 31;
    int wm = warp >> 3, wn = warp & 7;      // warp tile 64m x 32n
    int g = blockIdx.y;
    int m0 = blockIdx.x * BM;

    const float* Xg = X + ((size_t)g * BSZ + m0) * CH;
    const __nv_bfloat16* Qh = g_Qhi + (size_t)g * CH * CH;
    const __nv_bfloat16* Ql = g_Qlo + (size_t)g * CH * CH;

    // A staging: thread t -> row ar, cols [ac, ac+8) of the 128x32 chunk
    int ar = t >> 2, ac = (t & 3) * 8;
    // B cp.async: 32 rows x 32 granules of 16B; thread covers 2 (row,gran)
    int brow = t >> 4, bg0 = t & 15;

    float acc[4][4][4] = {};
    float4 xa[2];

    auto loadA = [&](int ch) {
        xa[0] = *(const float4*)(Xg + (size_t)ar * CH + ch * BK + ac);
        xa[1] = *(const float4*)(Xg + (size_t)ar * CH + ch * BK + ac + 4);
    };
    auto issueB = [&](int ch) {
        uint32_t d = sbase + (uint32_t)(ch & 1) * SBUF;
        #pragma unroll
        for (int gi = 0; gi < 2; ++gi) {
            int gr = bg0 + gi * 16;
            uint32_t off = (uint32_t)brow * 512 + (uint32_t)((gr ^ (brow & 7)) << 4);
            const __nv_bfloat16* sh = Qh + (size_t)(ch * BK + brow) * CH + gr * 8;
            const __nv_bfloat16* sl = Ql + (size_t)(ch * BK + brow) * CH + gr * 8;
            CP16(d + SB_H + off, sh);
            CP16(d + SB_L + off, sl);
        }
        asm volatile("cp.async.commit_group;" ::: "memory");
    };
    auto storeA = [&](int ch) {
        char* p = sm + (ch & 1) * SBUF;
        float f[8] = {xa[0].x, xa[0].y, xa[0].z, xa[0].w,
                      xa[1].x, xa[1].y, xa[1].z, xa[1].w};
        uint32_t h[4], l[4];
        #pragma unroll
        for (int i = 0; i < 4; ++i) {
            h[i] = pack_hi(f[2 * i], f[2 * i + 1]);
            l[i] = pack_lo(f[2 * i], f[2 * i + 1]);
        }
        uint32_t ao = ar * 80u + ac * 2u;
        *(uint4*)(p + SA_H + ao) = make_uint4(h[0], h[1], h[2], h[3]);
        *(uint4*)(p + SA_L + ao) = make_uint4(l[0], l[1], l[2], l[3]);
    };

    loadA(0);
    issueB(0);

    for (int ch = 0; ch < CH / BK; ++ch) {
        asm volatile("cp.async.wait_group 0;" ::: "memory");
        storeA(ch);
        __syncthreads();
        if (ch + 1 < CH / BK) { loadA(ch + 1); issueB(ch + 1); }

        uint32_t sb = sbase + (uint32_t)(ch & 1) * SBUF;
        #pragma unroll
        for (int ks = 0; ks < BK; ks += 16) {
            uint32_t ah[4][4], al[4][4];
            #pragma unroll
            for (int i = 0; i < 4; ++i) {
                uint32_t mrow = (uint32_t)(wm * 64 + i * 16 + (lane & 15));
                uint32_t kcol = (uint32_t)(ks + (lane >> 4) * 8);
                uint32_t addr = sb + SA_H + mrow * 80u + kcol * 2u;
                LDSM4(ah[i], addr);
                LDSM4(al[i], addr + (SA_L - SA_H));
            }
            #pragma unroll
            for (int p = 0; p < 2; ++p) {
                uint32_t bh[4], bl[4];
                uint32_t krow = (uint32_t)(ks + (lane & 15));
                uint32_t gran = (uint32_t)(wn * 4 + p * 2 + (lane >> 4));
                uint32_t addr = sb + SB_H + krow * 512u + ((gran ^ (krow & 7)) << 4);
                LDSM4T(bh, addr);
                LDSM4T(bl, addr + (SB_L - SB_H));
                #pragma unroll
                for (int i = 0; i < 4; ++i) {
                    MMA(acc[i][2 * p],     ah[i], bh[0], bh[1]);
                    MMA(acc[i][2 * p],     ah[i], bl[0], bl[1]);
                    MMA(acc[i][2 * p],     al[i], bh[0], bh[1]);
                    MMA(acc[i][2 * p + 1], ah[i], bh[2], bh[3]);
                    MMA(acc[i][2 * p + 1], ah[i], bl[2], bl[3]);
                    MMA(acc[i][2 * p + 1], al[i], bh[2], bh[3]);
                }
            }
        }
    }

    // epilogue
    #pragma unroll
    for (int i = 0; i < 4; ++i) {
        int row = m0 + wm * 64 + i * 16 + (lane >> 2);
        float* o0 = out + ((size_t)g * BSZ + row) * CH + wn * 32 + (lane & 3) * 2;
        #pragma unroll
        for (int j = 0; j < 4; ++j) {
            *(float2*)(o0 + j * 8)          = make_float2(acc[i][j][0], acc[i][j][1]);
            *(float2*)(o0 + 8 * CH + j * 8) = make_float2(acc[i][j][2], acc[i][j][3]);
        }
    }
}

// ---------------- entry ----------------------------------------------------
extern "C" void kernel_launch(void* const* d_in, const int* in_sizes, int n_in,
                              void* d_out, int out_size) {
    const float* x = (const float*)d_in[0];
    const float* w = (const float*)d_in[1];
    if (n_in >= 2 && in_sizes[0] < in_sizes[1]) {
        const float* tmp = x; x = w; w = tmp;
    }
    float* out = (float*)d_out;

    cudaFuncSetAttribute(main_mma, cudaFuncAttributeMaxDynamicSharedMemorySize,
                         SMEM_TOTAL);
    cudaFuncSetAttribute(g_mma, cudaFuncAttributeMaxDynamicSharedMemorySize, 65536);
    cudaFuncSetAttribute(q_mma, cudaFuncAttributeMaxDynamicSharedMemorySize, 65536);

    vsplit<<<GRP * CH * CH / 1024, 256>>>(w);

    dim3 ggrid(3, GRP);
    g_mma<<<ggrid, 256, 65536>>>();

    dim3 ygrid(CH / 32, GRP);
    y_kernel<<<ygrid, 256>>>(w);

    dim3 qgrid(4, GRP);
    q_mma<<<qgrid, 256, 65536>>>();

    dim3 mgrid(BSZ / BM, GRP);
    main_mma<<<mgrid, 512, SMEM_TOTAL>>>(x, out);
}